// round 1
// baseline (speedup 1.0000x reference)
#include <cuda_runtime.h>
#include <math.h>

#define NV 10000
#define NF 80000
#define NE 160000
#define SD 64
#define MD 64

// ---------------- persistent scratch (no allocation allowed) ----------------
__device__ float g_var_h[NV * SD];
__device__ float g_fac_h[NF * SD];
__device__ float g_nm_var[NV * MD];
__device__ float g_nm_fac[NF * MD];

// ---------------- zero ----------------
__global__ void zero_kernel(float* __restrict__ p, int n) {
    int i = blockIdx.x * blockDim.x + threadIdx.x;
    int stride = gridDim.x * blockDim.x;
    for (; i < n; i += stride) p[i] = 0.0f;
}

// ---------------- fused edge-message MLP (136 -> 128 -> 128 -> 64) ----------
// Tile = 64 edges, 256 threads. x staged in smem (stride 140 floats,
// conflict-free float4 phases), h1 stride 132. Weights streamed from L2 as
// LDG.128 with 4j x 4k x 2e register tile (16 FMA per weight vector).
// Epilogue: atomicAdd into segment-sum buffer nm[col].
#define EDGE_SMEM_FLOATS (64 * 140 + 64 * 132 + 128)
__global__ __launch_bounds__(256) void edge_mlp_kernel(
    const float* __restrict__ Ah, const float* __restrict__ Bh,
    const int* __restrict__ rowi, const int* __restrict__ coli,
    const float* __restrict__ feat,
    const float* __restrict__ W1, const float* __restrict__ b1,
    const float* __restrict__ W2, const float* __restrict__ b2,
    const float* __restrict__ W3, const float* __restrict__ b3,
    float* __restrict__ nm)
{
    extern __shared__ float smem[];
    float* xs  = smem;                 // [64][140], x then reused as h2
    float* h1s = smem + 64 * 140;      // [64][132]
    int*   rs  = (int*)(smem + 64 * 140 + 64 * 132);  // [64]
    int*   cs  = rs + 64;                              // [64]

    const int tid = threadIdx.x;
    const int e0  = blockIdx.x * 64;

    if (tid < 64)            rs[tid]      = rowi[e0 + tid];
    else if (tid < 128)      cs[tid - 64] = coli[e0 + tid - 64];
    __syncthreads();

    // gather x = [Ah[row] (64) | Bh[col] (64) | feat[row] (4) | feat[col] (4)]
    for (int i = tid; i < 64 * 136; i += 256) {
        int e = i / 136;
        int k = i - e * 136;
        float v;
        if (k < 64)        v = Ah[(size_t)rs[e] * 64 + k];
        else if (k < 128)  v = Bh[(size_t)cs[e] * 64 + (k - 64)];
        else if (k < 132)  v = feat[(size_t)rs[e] * 4 + (k - 128)];
        else               v = feat[(size_t)cs[e] * 4 + (k - 132)];
        xs[e * 140 + k] = v;
    }
    __syncthreads();

    const int warp = tid >> 5, lane = tid & 31;

    // ---- layer 1: 136 -> 128 (relu) ----
    #pragma unroll
    for (int jc = 0; jc < 4; jc++) {
        const int j0 = warp * 16 + jc * 4;
        float a0[4] = {0.f, 0.f, 0.f, 0.f};
        float a1[4] = {0.f, 0.f, 0.f, 0.f};
        #pragma unroll 2
        for (int k = 0; k < 136; k += 4) {
            float4 x0 = *(const float4*)(xs + lane * 140 + k);
            float4 x1 = *(const float4*)(xs + (lane + 32) * 140 + k);
            #pragma unroll
            for (int jj = 0; jj < 4; jj++) {
                float4 w = *(const float4*)(W1 + (size_t)(j0 + jj) * 136 + k);
                a0[jj] += w.x * x0.x + w.y * x0.y + w.z * x0.z + w.w * x0.w;
                a1[jj] += w.x * x1.x + w.y * x1.y + w.z * x1.z + w.w * x1.w;
            }
        }
        #pragma unroll
        for (int jj = 0; jj < 4; jj++) {
            float bb = b1[j0 + jj];
            h1s[lane * 132 + j0 + jj]        = fmaxf(a0[jj] + bb, 0.f);
            h1s[(lane + 32) * 132 + j0 + jj] = fmaxf(a1[jj] + bb, 0.f);
        }
    }
    __syncthreads();

    // ---- layer 2: 128 -> 128 (relu), h2 written into xs (stride 140) ----
    #pragma unroll
    for (int jc = 0; jc < 4; jc++) {
        const int j0 = warp * 16 + jc * 4;
        float a0[4] = {0.f, 0.f, 0.f, 0.f};
        float a1[4] = {0.f, 0.f, 0.f, 0.f};
        #pragma unroll 2
        for (int k = 0; k < 128; k += 4) {
            float4 x0 = *(const float4*)(h1s + lane * 132 + k);
            float4 x1 = *(const float4*)(h1s + (lane + 32) * 132 + k);
            #pragma unroll
            for (int jj = 0; jj < 4; jj++) {
                float4 w = *(const float4*)(W2 + (size_t)(j0 + jj) * 128 + k);
                a0[jj] += w.x * x0.x + w.y * x0.y + w.z * x0.z + w.w * x0.w;
                a1[jj] += w.x * x1.x + w.y * x1.y + w.z * x1.z + w.w * x1.w;
            }
        }
        #pragma unroll
        for (int jj = 0; jj < 4; jj++) {
            float bb = b2[j0 + jj];
            xs[lane * 140 + j0 + jj]        = fmaxf(a0[jj] + bb, 0.f);
            xs[(lane + 32) * 140 + j0 + jj] = fmaxf(a1[jj] + bb, 0.f);
        }
    }
    __syncthreads();

    // ---- layer 3: 128 -> 64, scatter-add into nm[col] ----
    #pragma unroll
    for (int jc = 0; jc < 2; jc++) {
        const int j0 = warp * 8 + jc * 4;
        float a0[4] = {0.f, 0.f, 0.f, 0.f};
        float a1[4] = {0.f, 0.f, 0.f, 0.f};
        #pragma unroll 2
        for (int k = 0; k < 128; k += 4) {
            float4 x0 = *(const float4*)(xs + lane * 140 + k);
            float4 x1 = *(const float4*)(xs + (lane + 32) * 140 + k);
            #pragma unroll
            for (int jj = 0; jj < 4; jj++) {
                float4 w = *(const float4*)(W3 + (size_t)(j0 + jj) * 128 + k);
                a0[jj] += w.x * x0.x + w.y * x0.y + w.z * x0.z + w.w * x0.w;
                a1[jj] += w.x * x1.x + w.y * x1.y + w.z * x1.z + w.w * x1.w;
            }
        }
        const size_t c0 = (size_t)cs[lane] * 64;
        const size_t c1 = (size_t)cs[lane + 32] * 64;
        #pragma unroll
        for (int jj = 0; jj < 4; jj++) {
            float bb = b3[j0 + jj];
            atomicAdd(nm + c0 + j0 + jj, a0[jj] + bb);
            atomicAdd(nm + c1 + j0 + jj, a1[jj] + bb);
        }
    }
}

// ---------------- GRU (input M=64, hidden S=64), 32 rows / block -----------
#define GRU_SMEM_FLOATS (32 * 68 * 2 + 32 * 384)
__global__ __launch_bounds__(256) void gru_kernel(
    float* __restrict__ h, const float* __restrict__ x,
    const float* __restrict__ wih, const float* __restrict__ whh,
    const float* __restrict__ bih, const float* __restrict__ bhh,
    int nrows)
{
    extern __shared__ float smem[];
    float* xsm = smem;                 // [32][68]
    float* hsm = smem + 32 * 68;       // [32][68]
    float* gs  = smem + 32 * 68 * 2;   // [32][384]: gi(192) | gh(192)

    const int tid = threadIdx.x;
    const int r0  = blockIdx.x * 32;

    for (int i = tid; i < 32 * 64; i += 256) {
        int e = i >> 6, k = i & 63;
        int r = r0 + e;
        float xv = 0.f, hv = 0.f;
        if (r < nrows) {
            xv = x[(size_t)r * 64 + k];
            hv = h[(size_t)r * 64 + k];
        }
        xsm[e * 68 + k] = xv;
        hsm[e * 68 + k] = hv;
    }
    __syncthreads();

    const int warp = tid >> 5, lane = tid & 31;
    const bool is_gh = warp >= 4;
    const float* W   = is_gh ? whh : wih;
    const float* bb  = is_gh ? bhh : bih;
    const float* src = is_gh ? hsm : xsm;
    const int    off = is_gh ? 192 : 0;
    const int    jb  = (warp & 3) * 48;

    #pragma unroll
    for (int jc = 0; jc < 12; jc++) {
        const int j0 = jb + jc * 4;
        float a[4] = {0.f, 0.f, 0.f, 0.f};
        #pragma unroll
        for (int k = 0; k < 64; k += 4) {
            float4 xv = *(const float4*)(src + lane * 68 + k);
            #pragma unroll
            for (int jj = 0; jj < 4; jj++) {
                float4 w = *(const float4*)(W + (size_t)(j0 + jj) * 64 + k);
                a[jj] += w.x * xv.x + w.y * xv.y + w.z * xv.z + w.w * xv.w;
            }
        }
        #pragma unroll
        for (int jj = 0; jj < 4; jj++)
            gs[lane * 384 + off + j0 + jj] = a[jj] + bb[j0 + jj];
    }
    __syncthreads();

    for (int i = tid; i < 32 * 64; i += 256) {
        int e = i >> 6, d = i & 63;
        int r = r0 + e;
        if (r >= nrows) continue;
        const float* g = gs + e * 384;
        float ir = g[d],        iz = g[64 + d],  in = g[128 + d];
        float hr = g[192 + d],  hz = g[256 + d], hn = g[320 + d];
        float rr = 1.f / (1.f + expf(-(ir + hr)));
        float zz = 1.f / (1.f + expf(-(iz + hz)));
        float nn = tanhf(in + rr * hn);
        float hv = hsm[e * 68 + d];
        h[(size_t)r * 64 + d] = (1.f - zz) * nn + zz * hv;
    }
}

// ---------------- readout: 64 -> 128 -> 128 -> 2, softmax -------------------
__global__ __launch_bounds__(256) void readout_kernel(
    const float* __restrict__ h,
    const float* __restrict__ W1, const float* __restrict__ b1,
    const float* __restrict__ W2, const float* __restrict__ b2,
    const float* __restrict__ W3, const float* __restrict__ b3,
    float* __restrict__ out, int nrows)
{
    __shared__ float hs[32 * 68];
    __shared__ float l1s[32 * 132];
    __shared__ float l2s[32 * 132];
    __shared__ float lg[64];

    const int tid = threadIdx.x;
    const int r0  = blockIdx.x * 32;

    for (int i = tid; i < 32 * 64; i += 256) {
        int e = i >> 6, k = i & 63;
        int r = r0 + e;
        hs[e * 68 + k] = (r < nrows) ? h[(size_t)r * 64 + k] : 0.f;
    }
    __syncthreads();

    const int warp = tid >> 5, lane = tid & 31;

    // layer1 64 -> 128
    #pragma unroll
    for (int jc = 0; jc < 4; jc++) {
        const int j0 = warp * 16 + jc * 4;
        float a[4] = {0.f, 0.f, 0.f, 0.f};
        #pragma unroll
        for (int k = 0; k < 64; k += 4) {
            float4 xv = *(const float4*)(hs + lane * 68 + k);
            #pragma unroll
            for (int jj = 0; jj < 4; jj++) {
                float4 w = *(const float4*)(W1 + (size_t)(j0 + jj) * 64 + k);
                a[jj] += w.x * xv.x + w.y * xv.y + w.z * xv.z + w.w * xv.w;
            }
        }
        #pragma unroll
        for (int jj = 0; jj < 4; jj++)
            l1s[lane * 132 + j0 + jj] = fmaxf(a[jj] + b1[j0 + jj], 0.f);
    }
    __syncthreads();

    // layer2 128 -> 128
    #pragma unroll
    for (int jc = 0; jc < 4; jc++) {
        const int j0 = warp * 16 + jc * 4;
        float a[4] = {0.f, 0.f, 0.f, 0.f};
        #pragma unroll 2
        for (int k = 0; k < 128; k += 4) {
            float4 xv = *(const float4*)(l1s + lane * 132 + k);
            #pragma unroll
            for (int jj = 0; jj < 4; jj++) {
                float4 w = *(const float4*)(W2 + (size_t)(j0 + jj) * 128 + k);
                a[jj] += w.x * xv.x + w.y * xv.y + w.z * xv.z + w.w * xv.w;
            }
        }
        #pragma unroll
        for (int jj = 0; jj < 4; jj++)
            l2s[lane * 132 + j0 + jj] = fmaxf(a[jj] + b2[j0 + jj], 0.f);
    }
    __syncthreads();

    // layer3: 2 logits per row, then 2-way softmax
    if (tid < 64) {
        int e = tid >> 1, j = tid & 1;
        float a = 0.f;
        #pragma unroll 4
        for (int k = 0; k < 128; k += 4) {
            float4 xv = *(const float4*)(l2s + e * 132 + k);
            float4 w  = *(const float4*)(W3 + (size_t)j * 128 + k);
            a += w.x * xv.x + w.y * xv.y + w.z * xv.z + w.w * xv.w;
        }
        lg[e * 2 + j] = a + b3[j];
    }
    __syncthreads();
    if (tid < 64) {
        int e = tid >> 1, j = tid & 1;
        int r = r0 + e;
        if (r < nrows) {
            float self  = lg[e * 2 + j];
            float other = lg[e * 2 + (j ^ 1)];
            out[(size_t)r * 2 + j] = 1.f / (1.f + expf(other - self));
        }
    }
}

// ---------------- launch -----------------------------------------------------
extern "C" void kernel_launch(void* const* d_in, const int* in_sizes, int n_in,
                              void* d_out, int out_size)
{
    const int*   f2v_row  = (const int*)d_in[0];
    const int*   f2v_col  = (const int*)d_in[1];
    const int*   v2f_row  = (const int*)d_in[2];
    const int*   v2f_col  = (const int*)d_in[3];
    const float* f2v_feat = (const float*)d_in[4];
    const float* v2f_feat = (const float*)d_in[5];
    const float* f2v_w1 = (const float*)d_in[6];
    const float* f2v_b1 = (const float*)d_in[7];
    const float* f2v_w2 = (const float*)d_in[8];
    const float* f2v_b2 = (const float*)d_in[9];
    const float* f2v_w3 = (const float*)d_in[10];
    const float* f2v_b3 = (const float*)d_in[11];
    const float* v2f_w1 = (const float*)d_in[12];
    const float* v2f_b1 = (const float*)d_in[13];
    const float* v2f_w2 = (const float*)d_in[14];
    const float* v2f_b2 = (const float*)d_in[15];
    const float* v2f_w3 = (const float*)d_in[16];
    const float* v2f_b3 = (const float*)d_in[17];
    const float* gf_wih = (const float*)d_in[18];
    const float* gf_whh = (const float*)d_in[19];
    const float* gf_bih = (const float*)d_in[20];
    const float* gf_bhh = (const float*)d_in[21];
    const float* gv_wih = (const float*)d_in[22];
    const float* gv_whh = (const float*)d_in[23];
    const float* gv_bih = (const float*)d_in[24];
    const float* gv_bhh = (const float*)d_in[25];
    const float* ro_w1  = (const float*)d_in[26];
    const float* ro_b1  = (const float*)d_in[27];
    const float* ro_w2  = (const float*)d_in[28];
    const float* ro_b2  = (const float*)d_in[29];
    const float* ro_w3  = (const float*)d_in[30];
    const float* ro_b3  = (const float*)d_in[31];
    float* out = (float*)d_out;

    float *var_h, *fac_h, *nm_var, *nm_fac;
    cudaGetSymbolAddress((void**)&var_h,  g_var_h);
    cudaGetSymbolAddress((void**)&fac_h,  g_fac_h);
    cudaGetSymbolAddress((void**)&nm_var, g_nm_var);
    cudaGetSymbolAddress((void**)&nm_fac, g_nm_fac);

    const int edge_smem = EDGE_SMEM_FLOATS * 4;
    const int gru_smem  = GRU_SMEM_FLOATS * 4;
    cudaFuncSetAttribute(edge_mlp_kernel, cudaFuncAttributeMaxDynamicSharedMemorySize, edge_smem);
    cudaFuncSetAttribute(gru_kernel,      cudaFuncAttributeMaxDynamicSharedMemorySize, gru_smem);

    zero_kernel<<<256, 256>>>(var_h, NV * SD);
    zero_kernel<<<512, 256>>>(fac_h, NF * SD);

    for (int s = 0; s < 5; s++) {
        // fac -> var
        zero_kernel<<<256, 256>>>(nm_var, NV * MD);
        edge_mlp_kernel<<<NE / 64, 256, edge_smem>>>(
            fac_h, var_h, f2v_row, f2v_col, f2v_feat,
            f2v_w1, f2v_b1, f2v_w2, f2v_b2, f2v_w3, f2v_b3, nm_var);
        gru_kernel<<<(NV + 31) / 32, 256, gru_smem>>>(
            var_h, nm_var, gf_wih, gf_whh, gf_bih, gf_bhh, NV);

        // var -> fac
        zero_kernel<<<512, 256>>>(nm_fac, NF * MD);
        edge_mlp_kernel<<<NE / 64, 256, edge_smem>>>(
            var_h, fac_h, v2f_row, v2f_col, v2f_feat,
            v2f_w1, v2f_b1, v2f_w2, v2f_b2, v2f_w3, v2f_b3, nm_fac);
        gru_kernel<<<NF / 32, 256, gru_smem>>>(
            fac_h, nm_fac, gv_wih, gv_whh, gv_bih, gv_bhh, NF);
    }

    readout_kernel<<<(NV + 31) / 32, 256>>>(
        var_h, ro_w1, ro_b1, ro_w2, ro_b2, ro_w3, ro_b3, out, NV);
}

// round 2
// speedup vs baseline: 1.0009x; 1.0009x over previous
#include <cuda_runtime.h>
#include <math.h>

#define NV 10000
#define NF 80000
#define NE 160000
#define SD 64
#define MD 64

// ---------------- persistent scratch (no allocation allowed) ----------------
__device__ float g_var_h[NV * SD];
__device__ float g_fac_h[NF * SD];
__device__ float g_nm_var[NV * MD];
__device__ float g_nm_fac[NF * MD];

// ---------------- zero ----------------
__global__ void zero_kernel(float* __restrict__ p, int n) {
    int i = blockIdx.x * blockDim.x + threadIdx.x;
    int stride = gridDim.x * blockDim.x;
    for (; i < n; i += stride) p[i] = 0.0f;
}

// ---------------- fused edge-message MLP (136 -> 128 -> 128 -> 64) ----------
// Tile = 64 edges, 256 threads. x staged in smem (stride 140 floats,
// conflict-free float4 phases), h1 stride 132. Weights streamed from L2 as
// LDG.128 with 4j x 4k x 2e register tile (16 FMA per weight vector).
// Epilogue: atomicAdd into segment-sum buffer nm[col].
#define EDGE_SMEM_FLOATS (64 * 140 + 64 * 132 + 128)
__global__ __launch_bounds__(256) void edge_mlp_kernel(
    const float* __restrict__ Ah, const float* __restrict__ Bh,
    const int* __restrict__ rowi, const int* __restrict__ coli,
    const float* __restrict__ feat,
    const float* __restrict__ W1, const float* __restrict__ b1,
    const float* __restrict__ W2, const float* __restrict__ b2,
    const float* __restrict__ W3, const float* __restrict__ b3,
    float* __restrict__ nm)
{
    extern __shared__ float smem[];
    float* xs  = smem;                 // [64][140], x then reused as h2
    float* h1s = smem + 64 * 140;      // [64][132]
    int*   rs  = (int*)(smem + 64 * 140 + 64 * 132);  // [64]
    int*   cs  = rs + 64;                              // [64]

    const int tid = threadIdx.x;
    const int e0  = blockIdx.x * 64;

    if (tid < 64)            rs[tid]      = rowi[e0 + tid];
    else if (tid < 128)      cs[tid - 64] = coli[e0 + tid - 64];
    __syncthreads();

    // gather x = [Ah[row] (64) | Bh[col] (64) | feat[row] (4) | feat[col] (4)]
    for (int i = tid; i < 64 * 136; i += 256) {
        int e = i / 136;
        int k = i - e * 136;
        float v;
        if (k < 64)        v = Ah[(size_t)rs[e] * 64 + k];
        else if (k < 128)  v = Bh[(size_t)cs[e] * 64 + (k - 64)];
        else if (k < 132)  v = feat[(size_t)rs[e] * 4 + (k - 128)];
        else               v = feat[(size_t)cs[e] * 4 + (k - 132)];
        xs[e * 140 + k] = v;
    }
    __syncthreads();

    const int warp = tid >> 5, lane = tid & 31;

    // ---- layer 1: 136 -> 128 (relu) ----
    #pragma unroll
    for (int jc = 0; jc < 4; jc++) {
        const int j0 = warp * 16 + jc * 4;
        float a0[4] = {0.f, 0.f, 0.f, 0.f};
        float a1[4] = {0.f, 0.f, 0.f, 0.f};
        #pragma unroll 2
        for (int k = 0; k < 136; k += 4) {
            float4 x0 = *(const float4*)(xs + lane * 140 + k);
            float4 x1 = *(const float4*)(xs + (lane + 32) * 140 + k);
            #pragma unroll
            for (int jj = 0; jj < 4; jj++) {
                float4 w = *(const float4*)(W1 + (size_t)(j0 + jj) * 136 + k);
                a0[jj] += w.x * x0.x + w.y * x0.y + w.z * x0.z + w.w * x0.w;
                a1[jj] += w.x * x1.x + w.y * x1.y + w.z * x1.z + w.w * x1.w;
            }
        }
        #pragma unroll
        for (int jj = 0; jj < 4; jj++) {
            float bb = b1[j0 + jj];
            h1s[lane * 132 + j0 + jj]        = fmaxf(a0[jj] + bb, 0.f);
            h1s[(lane + 32) * 132 + j0 + jj] = fmaxf(a1[jj] + bb, 0.f);
        }
    }
    __syncthreads();

    // ---- layer 2: 128 -> 128 (relu), h2 written into xs (stride 140) ----
    #pragma unroll
    for (int jc = 0; jc < 4; jc++) {
        const int j0 = warp * 16 + jc * 4;
        float a0[4] = {0.f, 0.f, 0.f, 0.f};
        float a1[4] = {0.f, 0.f, 0.f, 0.f};
        #pragma unroll 2
        for (int k = 0; k < 128; k += 4) {
            float4 x0 = *(const float4*)(h1s + lane * 132 + k);
            float4 x1 = *(const float4*)(h1s + (lane + 32) * 132 + k);
            #pragma unroll
            for (int jj = 0; jj < 4; jj++) {
                float4 w = *(const float4*)(W2 + (size_t)(j0 + jj) * 128 + k);
                a0[jj] += w.x * x0.x + w.y * x0.y + w.z * x0.z + w.w * x0.w;
                a1[jj] += w.x * x1.x + w.y * x1.y + w.z * x1.z + w.w * x1.w;
            }
        }
        #pragma unroll
        for (int jj = 0; jj < 4; jj++) {
            float bb = b2[j0 + jj];
            xs[lane * 140 + j0 + jj]        = fmaxf(a0[jj] + bb, 0.f);
            xs[(lane + 32) * 140 + j0 + jj] = fmaxf(a1[jj] + bb, 0.f);
        }
    }
    __syncthreads();

    // ---- layer 3: 128 -> 64, scatter-add into nm[col] ----
    #pragma unroll
    for (int jc = 0; jc < 2; jc++) {
        const int j0 = warp * 8 + jc * 4;
        float a0[4] = {0.f, 0.f, 0.f, 0.f};
        float a1[4] = {0.f, 0.f, 0.f, 0.f};
        #pragma unroll 2
        for (int k = 0; k < 128; k += 4) {
            float4 x0 = *(const float4*)(xs + lane * 140 + k);
            float4 x1 = *(const float4*)(xs + (lane + 32) * 140 + k);
            #pragma unroll
            for (int jj = 0; jj < 4; jj++) {
                float4 w = *(const float4*)(W3 + (size_t)(j0 + jj) * 128 + k);
                a0[jj] += w.x * x0.x + w.y * x0.y + w.z * x0.z + w.w * x0.w;
                a1[jj] += w.x * x1.x + w.y * x1.y + w.z * x1.z + w.w * x1.w;
            }
        }
        const size_t c0 = (size_t)cs[lane] * 64;
        const size_t c1 = (size_t)cs[lane + 32] * 64;
        #pragma unroll
        for (int jj = 0; jj < 4; jj++) {
            float bb = b3[j0 + jj];
            atomicAdd(nm + c0 + j0 + jj, a0[jj] + bb);
            atomicAdd(nm + c1 + j0 + jj, a1[jj] + bb);
        }
    }
}

// ---------------- GRU (input M=64, hidden S=64), 32 rows / block -----------
#define GRU_SMEM_FLOATS (32 * 68 * 2 + 32 * 384)
__global__ __launch_bounds__(256) void gru_kernel(
    float* __restrict__ h, const float* __restrict__ x,
    const float* __restrict__ wih, const float* __restrict__ whh,
    const float* __restrict__ bih, const float* __restrict__ bhh,
    int nrows)
{
    extern __shared__ float smem[];
    float* xsm = smem;                 // [32][68]
    float* hsm = smem + 32 * 68;       // [32][68]
    float* gs  = smem + 32 * 68 * 2;   // [32][384]: gi(192) | gh(192)

    const int tid = threadIdx.x;
    const int r0  = blockIdx.x * 32;

    for (int i = tid; i < 32 * 64; i += 256) {
        int e = i >> 6, k = i & 63;
        int r = r0 + e;
        float xv = 0.f, hv = 0.f;
        if (r < nrows) {
            xv = x[(size_t)r * 64 + k];
            hv = h[(size_t)r * 64 + k];
        }
        xsm[e * 68 + k] = xv;
        hsm[e * 68 + k] = hv;
    }
    __syncthreads();

    const int warp = tid >> 5, lane = tid & 31;
    const bool is_gh = warp >= 4;
    const float* W   = is_gh ? whh : wih;
    const float* bb  = is_gh ? bhh : bih;
    const float* src = is_gh ? hsm : xsm;
    const int    off = is_gh ? 192 : 0;
    const int    jb  = (warp & 3) * 48;

    #pragma unroll
    for (int jc = 0; jc < 12; jc++) {
        const int j0 = jb + jc * 4;
        float a[4] = {0.f, 0.f, 0.f, 0.f};
        #pragma unroll
        for (int k = 0; k < 64; k += 4) {
            float4 xv = *(const float4*)(src + lane * 68 + k);
            #pragma unroll
            for (int jj = 0; jj < 4; jj++) {
                float4 w = *(const float4*)(W + (size_t)(j0 + jj) * 64 + k);
                a[jj] += w.x * xv.x + w.y * xv.y + w.z * xv.z + w.w * xv.w;
            }
        }
        #pragma unroll
        for (int jj = 0; jj < 4; jj++)
            gs[lane * 384 + off + j0 + jj] = a[jj] + bb[j0 + jj];
    }
    __syncthreads();

    for (int i = tid; i < 32 * 64; i += 256) {
        int e = i >> 6, d = i & 63;
        int r = r0 + e;
        if (r >= nrows) continue;
        const float* g = gs + e * 384;
        float ir = g[d],        iz = g[64 + d],  in = g[128 + d];
        float hr = g[192 + d],  hz = g[256 + d], hn = g[320 + d];
        float rr = 1.f / (1.f + expf(-(ir + hr)));
        float zz = 1.f / (1.f + expf(-(iz + hz)));
        float nn = tanhf(in + rr * hn);
        float hv = hsm[e * 68 + d];
        h[(size_t)r * 64 + d] = (1.f - zz) * nn + zz * hv;
    }
}

// ---------------- readout: 64 -> 128 -> 128 -> 2, softmax -------------------
__global__ __launch_bounds__(256) void readout_kernel(
    const float* __restrict__ h,
    const float* __restrict__ W1, const float* __restrict__ b1,
    const float* __restrict__ W2, const float* __restrict__ b2,
    const float* __restrict__ W3, const float* __restrict__ b3,
    float* __restrict__ out, int nrows)
{
    __shared__ float hs[32 * 68];
    __shared__ float l1s[32 * 132];
    __shared__ float l2s[32 * 132];
    __shared__ float lg[64];

    const int tid = threadIdx.x;
    const int r0  = blockIdx.x * 32;

    for (int i = tid; i < 32 * 64; i += 256) {
        int e = i >> 6, k = i & 63;
        int r = r0 + e;
        hs[e * 68 + k] = (r < nrows) ? h[(size_t)r * 64 + k] : 0.f;
    }
    __syncthreads();

    const int warp = tid >> 5, lane = tid & 31;

    // layer1 64 -> 128
    #pragma unroll
    for (int jc = 0; jc < 4; jc++) {
        const int j0 = warp * 16 + jc * 4;
        float a[4] = {0.f, 0.f, 0.f, 0.f};
        #pragma unroll
        for (int k = 0; k < 64; k += 4) {
            float4 xv = *(const float4*)(hs + lane * 68 + k);
            #pragma unroll
            for (int jj = 0; jj < 4; jj++) {
                float4 w = *(const float4*)(W1 + (size_t)(j0 + jj) * 64 + k);
                a[jj] += w.x * xv.x + w.y * xv.y + w.z * xv.z + w.w * xv.w;
            }
        }
        #pragma unroll
        for (int jj = 0; jj < 4; jj++)
            l1s[lane * 132 + j0 + jj] = fmaxf(a[jj] + b1[j0 + jj], 0.f);
    }
    __syncthreads();

    // layer2 128 -> 128
    #pragma unroll
    for (int jc = 0; jc < 4; jc++) {
        const int j0 = warp * 16 + jc * 4;
        float a[4] = {0.f, 0.f, 0.f, 0.f};
        #pragma unroll 2
        for (int k = 0; k < 128; k += 4) {
            float4 xv = *(const float4*)(l1s + lane * 132 + k);
            #pragma unroll
            for (int jj = 0; jj < 4; jj++) {
                float4 w = *(const float4*)(W2 + (size_t)(j0 + jj) * 128 + k);
                a[jj] += w.x * xv.x + w.y * xv.y + w.z * xv.z + w.w * xv.w;
            }
        }
        #pragma unroll
        for (int jj = 0; jj < 4; jj++)
            l2s[lane * 132 + j0 + jj] = fmaxf(a[jj] + b2[j0 + jj], 0.f);
    }
    __syncthreads();

    // layer3: 2 logits per row, then 2-way softmax
    if (tid < 64) {
        int e = tid >> 1, j = tid & 1;
        float a = 0.f;
        #pragma unroll 4
        for (int k = 0; k < 128; k += 4) {
            float4 xv = *(const float4*)(l2s + e * 132 + k);
            float4 w  = *(const float4*)(W3 + (size_t)j * 128 + k);
            a += w.x * xv.x + w.y * xv.y + w.z * xv.z + w.w * xv.w;
        }
        lg[e * 2 + j] = a + b3[j];
    }
    __syncthreads();
    if (tid < 64) {
        int e = tid >> 1, j = tid & 1;
        int r = r0 + e;
        if (r < nrows) {
            float self  = lg[e * 2 + j];
            float other = lg[e * 2 + (j ^ 1)];
            out[(size_t)r * 2 + j] = 1.f / (1.f + expf(other - self));
        }
    }
}

// ---------------- launch -----------------------------------------------------
extern "C" void kernel_launch(void* const* d_in, const int* in_sizes, int n_in,
                              void* d_out, int out_size)
{
    const int*   f2v_row  = (const int*)d_in[0];
    const int*   f2v_col  = (const int*)d_in[1];
    const int*   v2f_row  = (const int*)d_in[2];
    const int*   v2f_col  = (const int*)d_in[3];
    const float* f2v_feat = (const float*)d_in[4];
    const float* v2f_feat = (const float*)d_in[5];
    const float* f2v_w1 = (const float*)d_in[6];
    const float* f2v_b1 = (const float*)d_in[7];
    const float* f2v_w2 = (const float*)d_in[8];
    const float* f2v_b2 = (const float*)d_in[9];
    const float* f2v_w3 = (const float*)d_in[10];
    const float* f2v_b3 = (const float*)d_in[11];
    const float* v2f_w1 = (const float*)d_in[12];
    const float* v2f_b1 = (const float*)d_in[13];
    const float* v2f_w2 = (const float*)d_in[14];
    const float* v2f_b2 = (const float*)d_in[15];
    const float* v2f_w3 = (const float*)d_in[16];
    const float* v2f_b3 = (const float*)d_in[17];
    const float* gf_wih = (const float*)d_in[18];
    const float* gf_whh = (const float*)d_in[19];
    const float* gf_bih = (const float*)d_in[20];
    const float* gf_bhh = (const float*)d_in[21];
    const float* gv_wih = (const float*)d_in[22];
    const float* gv_whh = (const float*)d_in[23];
    const float* gv_bih = (const float*)d_in[24];
    const float* gv_bhh = (const float*)d_in[25];
    const float* ro_w1  = (const float*)d_in[26];
    const float* ro_b1  = (const float*)d_in[27];
    const float* ro_w2  = (const float*)d_in[28];
    const float* ro_b2  = (const float*)d_in[29];
    const float* ro_w3  = (const float*)d_in[30];
    const float* ro_b3  = (const float*)d_in[31];
    float* out = (float*)d_out;

    float *var_h, *fac_h, *nm_var, *nm_fac;
    cudaGetSymbolAddress((void**)&var_h,  g_var_h);
    cudaGetSymbolAddress((void**)&fac_h,  g_fac_h);
    cudaGetSymbolAddress((void**)&nm_var, g_nm_var);
    cudaGetSymbolAddress((void**)&nm_fac, g_nm_fac);

    const int edge_smem = EDGE_SMEM_FLOATS * 4;
    const int gru_smem  = GRU_SMEM_FLOATS * 4;
    cudaFuncSetAttribute(edge_mlp_kernel, cudaFuncAttributeMaxDynamicSharedMemorySize, edge_smem);
    cudaFuncSetAttribute(gru_kernel,      cudaFuncAttributeMaxDynamicSharedMemorySize, gru_smem);

    zero_kernel<<<256, 256>>>(var_h, NV * SD);
    zero_kernel<<<512, 256>>>(fac_h, NF * SD);

    for (int s = 0; s < 5; s++) {
        // fac -> var
        zero_kernel<<<256, 256>>>(nm_var, NV * MD);
        edge_mlp_kernel<<<NE / 64, 256, edge_smem>>>(
            fac_h, var_h, f2v_row, f2v_col, f2v_feat,
            f2v_w1, f2v_b1, f2v_w2, f2v_b2, f2v_w3, f2v_b3, nm_var);
        gru_kernel<<<(NV + 31) / 32, 256, gru_smem>>>(
            var_h, nm_var, gf_wih, gf_whh, gf_bih, gf_bhh, NV);

        // var -> fac
        zero_kernel<<<512, 256>>>(nm_fac, NF * MD);
        edge_mlp_kernel<<<NE / 64, 256, edge_smem>>>(
            var_h, fac_h, v2f_row, v2f_col, v2f_feat,
            v2f_w1, v2f_b1, v2f_w2, v2f_b2, v2f_w3, v2f_b3, nm_fac);
        gru_kernel<<<NF / 32, 256, gru_smem>>>(
            fac_h, nm_fac, gv_wih, gv_whh, gv_bih, gv_bhh, NF);
    }

    readout_kernel<<<(NV + 31) / 32, 256>>>(
        var_h, ro_w1, ro_b1, ro_w2, ro_b2, ro_w3, ro_b3, out, NV);
}

// round 5
// speedup vs baseline: 2.2912x; 2.2891x over previous
#include <cuda_runtime.h>
#include <cuda_bf16.h>
#include <cstdint>
#include <math.h>

#define NV 10000
#define NF 80000
#define NE 160000

// row stride for all bf16 tiles: 152 elements = 304 bytes (19*16B, LDSM conflict-free)
#define RSTRIDE 304
#define A_LO_OFF 38912          // 128 rows * 304
#define W1_PLANE 38912          // 128 rows
#define W3_PLANE 19456          // 64 rows

// ---------------- persistent scratch ----------------
__device__ float g_var_h[NV * 64];
__device__ float g_fac_h[NF * 64];
__device__ float g_nm_var[NV * 64];
__device__ float g_nm_fac[NF * 64];
// per direction: [W1 hi+lo 77824][W2 hi+lo 77824][W3 hi+lo 38912] = 194560
__device__ __align__(256) unsigned char g_wpack_f2v[194560];
__device__ __align__(256) unsigned char g_wpack_v2f[194560];

// ---------------- PTX helpers (sm_90-baseline only; NO tcgen05) -------------
__device__ __forceinline__ uint32_t smem_u32(const void* p) {
    uint32_t a;
    asm("{ .reg .u64 t; cvta.to.shared.u64 t, %1; cvt.u32.u64 %0, t; }" : "=r"(a) : "l"(p));
    return a;
}
#define MBARRIER_INIT(mbar, cnt) \
    asm volatile("mbarrier.init.shared.b64 [%0], %1;" :: "r"(mbar), "r"(cnt) : "memory")
#define MBARRIER_EXPECT_TX(mbar, bytes) \
    asm volatile("mbarrier.arrive.expect_tx.shared.b64 _, [%0], %1;" :: "r"(mbar), "r"(bytes) : "memory")
#define MBARRIER_WAIT_PARITY(mbar, ph) do { \
    asm volatile("{\n\t.reg .pred P1;\n\t" \
        "W_%=:\n\tmbarrier.try_wait.parity.acquire.cta.shared::cta.b64 P1, [%0], %1, 0x989680;\n\t" \
        "@P1 bra.uni D_%=;\n\tbra.uni W_%=;\n\tD_%=:\n\t}" \
        :: "r"(mbar), "r"(ph) : "memory"); \
} while (0)

__device__ __forceinline__ void bulk_copy_g2s(uint32_t dst, const void* src,
                                              uint32_t bytes, uint32_t mbar) {
    asm volatile(
        "cp.async.bulk.shared::cluster.global.mbarrier::complete_tx::bytes [%0], [%1], %2, [%3];"
        :: "r"(dst), "l"(src), "r"(bytes), "r"(mbar) : "memory");
}
__device__ __forceinline__ void ldsm4(uint32_t addr, uint32_t* r) {
    asm volatile("ldmatrix.sync.aligned.m8n8.x4.shared.b16 {%0,%1,%2,%3}, [%4];"
        : "=r"(r[0]), "=r"(r[1]), "=r"(r[2]), "=r"(r[3]) : "r"(addr));
}
__device__ __forceinline__ void mma16816(float* d, const uint32_t* a, const uint32_t* b) {
    asm volatile("mma.sync.aligned.m16n8k16.row.col.f32.bf16.bf16.f32 "
        "{%0,%1,%2,%3}, {%4,%5,%6,%7}, {%8,%9}, {%0,%1,%2,%3};"
        : "+f"(d[0]), "+f"(d[1]), "+f"(d[2]), "+f"(d[3])
        : "r"(a[0]), "r"(a[1]), "r"(a[2]), "r"(a[3]), "r"(b[0]), "r"(b[1]));
}

// ---------------- zero ----------------
__global__ void zero_kernel(float* __restrict__ p, int n) {
    int i = blockIdx.x * blockDim.x + threadIdx.x;
    for (; i < n; i += gridDim.x * blockDim.x) p[i] = 0.0f;
}

// ---------------- weight pre-pack: fp32 -> hi/lo bf16, padded row-major -----
__global__ void pack_weights_kernel(unsigned char* __restrict__ dst,
                                    const float* __restrict__ W,
                                    int nrows, int kin) {
    const int total = nrows * 152;
    const int plane = nrows * RSTRIDE;
    for (int i = blockIdx.x * blockDim.x + threadIdx.x; i < total;
         i += gridDim.x * blockDim.x) {
        int n = i / 152, k = i - n * 152;
        float v = (k < kin) ? W[n * kin + k] : 0.0f;
        __nv_bfloat16 hi = __float2bfloat16(v);
        __nv_bfloat16 lo = __float2bfloat16(v - __bfloat162float(hi));
        uint32_t off = (uint32_t)n * RSTRIDE + (uint32_t)k * 2;
        *(__nv_bfloat16*)(dst + off) = hi;
        *(__nv_bfloat16*)(dst + plane + off) = lo;
    }
}

// ---------------- mma layer: [128 x K] x [N x K]^T, warp tile 32m x (16*NPAIR)n
template<int KCH, int NPAIR>
__device__ __forceinline__ void layer_mma(
    uint32_t aA, uint32_t aW, uint32_t wloOff,
    int lane, int mbase, int nbase, float* acc)
{
    const uint32_t aRow = aA + (uint32_t)(mbase + (lane & 15)) * RSTRIDE + ((lane >> 4) << 4);
    const uint32_t bRow = aW + (uint32_t)(nbase + (lane & 7) + ((lane >> 4) << 3)) * RSTRIDE
                        + (((lane >> 3) & 1) << 4);
    #pragma unroll
    for (int kc = 0; kc < KCH; kc++) {
        uint32_t ah[8], al[8];
        ldsm4(aRow + kc * 32, ah);
        ldsm4(aRow + 16 * RSTRIDE + kc * 32, ah + 4);
        ldsm4(aRow + A_LO_OFF + kc * 32, al);
        ldsm4(aRow + A_LO_OFF + 16 * RSTRIDE + kc * 32, al + 4);
        #pragma unroll
        for (int np = 0; np < NPAIR; np++) {
            uint32_t bh[4], bl[4];
            ldsm4(bRow + np * 16 * RSTRIDE + kc * 32, bh);
            ldsm4(bRow + wloOff + np * 16 * RSTRIDE + kc * 32, bl);
            #pragma unroll
            for (int m = 0; m < 2; m++) {
                #pragma unroll
                for (int h = 0; h < 2; h++) {
                    float* d = acc + ((m * NPAIR + np) * 2 + h) * 4;
                    mma16816(d, ah + m * 4, bh + h * 2);
                    mma16816(d, ah + m * 4, bl + h * 2);
                    mma16816(d, al + m * 4, bh + h * 2);
                }
            }
        }
    }
}

// epilogue layers 1/2: +bias, relu, hi/lo split, write back into A tile
__device__ __forceinline__ void epi12(unsigned char* Ab, const float* bias,
                                      int lane, int mbase, int nbase, const float* acc)
{
    #pragma unroll
    for (int m = 0; m < 2; m++)
        #pragma unroll
        for (int np = 0; np < 2; np++)
            #pragma unroll
            for (int h = 0; h < 2; h++) {
                const float* d = acc + ((m * 2 + np) * 2 + h) * 4;
                int c = nbase + np * 16 + h * 8 + 2 * (lane & 3);
                int r = mbase + m * 16 + (lane >> 2);
                float b0 = bias[c], b1 = bias[c + 1];
                float v0 = fmaxf(d[0] + b0, 0.f), v1 = fmaxf(d[1] + b1, 0.f);
                float v2 = fmaxf(d[2] + b0, 0.f), v3 = fmaxf(d[3] + b1, 0.f);
                __nv_bfloat162 hA = __floats2bfloat162_rn(v0, v1);
                __nv_bfloat162 lA = __floats2bfloat162_rn(v0 - __low2float(hA),
                                                          v1 - __high2float(hA));
                __nv_bfloat162 hB = __floats2bfloat162_rn(v2, v3);
                __nv_bfloat162 lB = __floats2bfloat162_rn(v2 - __low2float(hB),
                                                          v3 - __high2float(hB));
                uint32_t o0 = (uint32_t)r * RSTRIDE + (uint32_t)c * 2;
                uint32_t o1 = o0 + 8u * RSTRIDE;
                *(uint32_t*)(Ab + o0)            = *(uint32_t*)&hA;
                *(uint32_t*)(Ab + A_LO_OFF + o0) = *(uint32_t*)&lA;
                *(uint32_t*)(Ab + o1)            = *(uint32_t*)&hB;
                *(uint32_t*)(Ab + A_LO_OFF + o1) = *(uint32_t*)&lB;
            }
}

// ---------------- fused edge MLP: 136->128->128->64 on HMMA ----------------
// smem: A hi[38912] lo[38912] | W[77824] | rs[512] cs[512] bias[1280] mbar[16]
#define SM_A    0
#define SM_W    77824
#define SM_RS   155648
#define SM_CS   156160
#define SM_BIAS 156672
#define SM_MBW  157952
#define EDGE_SMEM_BYTES 157984
__global__ __launch_bounds__(512, 1) void edge_mma_kernel(
    const float* __restrict__ Ah, const float* __restrict__ Bh,
    const int* __restrict__ rowi, const int* __restrict__ coli,
    const float* __restrict__ feat,
    const unsigned char* __restrict__ wsrc,
    const float* __restrict__ b1, const float* __restrict__ b2,
    const float* __restrict__ b3,
    float* __restrict__ nm)
{
    extern __shared__ __align__(256) unsigned char sm[];
    const uint32_t smb = smem_u32(sm);
    const int tid = threadIdx.x;
    const int e0 = blockIdx.x * 128;

    int*   rs     = (int*)(sm + SM_RS);
    int*   cs     = (int*)(sm + SM_CS);
    float* bias_s = (float*)(sm + SM_BIAS);
    const uint32_t mbw = smb + SM_MBW;

    if (tid == 0) MBARRIER_INIT(mbw, 1u);
    __syncthreads();
    if (tid == 0) {                       // W1 (hi+lo) copy overlaps gather
        MBARRIER_EXPECT_TX(mbw, 77824u);
        bulk_copy_g2s(smb + SM_W, wsrc, 77824u, mbw);
    }
    if (tid < 128)       rs[tid] = rowi[e0 + tid];
    else if (tid < 256)  cs[tid - 128] = coli[e0 + tid - 128];
    for (int i = tid; i < 320; i += 512)
        bias_s[i] = (i < 128) ? b1[i] : (i < 256 ? b2[i - 128] : b3[i - 256]);
    __syncthreads();   // rs/cs must be visible before the gather reads them

    // gather A1 = [Ah[row](64) | Bh[col](64) | feat[row](4) | feat[col](4) | 0(16)]
    for (int i = tid; i < 128 * 38; i += 512) {
        int e = i / 38, q = i - e * 38;
        float4 x;
        if (q < 16)       x = *(const float4*)(Ah + (size_t)rs[e] * 64 + q * 4);
        else if (q < 32)  x = *(const float4*)(Bh + (size_t)cs[e] * 64 + (q - 16) * 4);
        else if (q == 32) x = *(const float4*)(feat + (size_t)rs[e] * 4);
        else if (q == 33) x = *(const float4*)(feat + (size_t)cs[e] * 4);
        else              x = make_float4(0.f, 0.f, 0.f, 0.f);
        __nv_bfloat162 h01 = __floats2bfloat162_rn(x.x, x.y);
        __nv_bfloat162 h23 = __floats2bfloat162_rn(x.z, x.w);
        __nv_bfloat162 l01 = __floats2bfloat162_rn(x.x - __low2float(h01), x.y - __high2float(h01));
        __nv_bfloat162 l23 = __floats2bfloat162_rn(x.z - __low2float(h23), x.w - __high2float(h23));
        uint32_t off = (uint32_t)e * RSTRIDE + (uint32_t)q * 8;
        *(uint2*)(sm + off)            = make_uint2(*(uint32_t*)&h01, *(uint32_t*)&h23);
        *(uint2*)(sm + A_LO_OFF + off) = make_uint2(*(uint32_t*)&l01, *(uint32_t*)&l23);
    }
    __syncthreads();

    const int w = tid >> 5, lane = tid & 31;
    const int mbase = (w & 3) * 32;
    const int nb32  = (w >> 2) * 32;
    float acc[32];

    // ---- layer 1: K=144 (9 chunks), N=128 ----
    MBARRIER_WAIT_PARITY(mbw, 0);
    #pragma unroll
    for (int i = 0; i < 32; i++) acc[i] = 0.f;
    layer_mma<9, 2>(smb, smb + SM_W, W1_PLANE, lane, mbase, nb32, acc);
    __syncthreads();
    if (tid == 0) {
        MBARRIER_EXPECT_TX(mbw, 77824u);
        bulk_copy_g2s(smb + SM_W, wsrc + 77824, 77824u, mbw);
    }
    epi12(sm, bias_s, lane, mbase, nb32, acc);
    __syncthreads();

    // ---- layer 2: K=128 (8 chunks), N=128 ----
    MBARRIER_WAIT_PARITY(mbw, 1);
    #pragma unroll
    for (int i = 0; i < 32; i++) acc[i] = 0.f;
    layer_mma<8, 2>(smb, smb + SM_W, W1_PLANE, lane, mbase, nb32, acc);
    __syncthreads();
    if (tid == 0) {
        MBARRIER_EXPECT_TX(mbw, 38912u);
        bulk_copy_g2s(smb + SM_W, wsrc + 155648, 38912u, mbw);
    }
    epi12(sm, bias_s + 128, lane, mbase, nb32, acc);
    __syncthreads();

    // ---- layer 3: K=128 (8 chunks), N=64, scatter-add ----
    MBARRIER_WAIT_PARITY(mbw, 0);
    #pragma unroll
    for (int i = 0; i < 16; i++) acc[i] = 0.f;
    const int nb16 = (w >> 2) * 16;
    layer_mma<8, 1>(smb, smb + SM_W, W3_PLANE, lane, mbase, nb16, acc);

    #pragma unroll
    for (int m = 0; m < 2; m++)
        #pragma unroll
        for (int h = 0; h < 2; h++) {
            const float* d = acc + (m * 2 + h) * 4;
            int c = nb16 + h * 8 + 2 * (lane & 3);
            int r = mbase + m * 16 + (lane >> 2);
            float b0 = bias_s[256 + c], b1v = bias_s[256 + c + 1];
            float* p0 = nm + (size_t)cs[r] * 64 + c;
            float* p1 = nm + (size_t)cs[r + 8] * 64 + c;
            atomicAdd(p0,     d[0] + b0);
            atomicAdd(p0 + 1, d[1] + b1v);
            atomicAdd(p1,     d[2] + b0);
            atomicAdd(p1 + 1, d[3] + b1v);
        }
}

// ---------------- GRU; zeroes x (nm) after consuming it ----------------
#define GRU_SMEM_FLOATS (32 * 68 * 2 + 32 * 384)
__global__ __launch_bounds__(256) void gru_kernel(
    float* __restrict__ h, float* __restrict__ x,
    const float* __restrict__ wih, const float* __restrict__ whh,
    const float* __restrict__ bih, const float* __restrict__ bhh,
    int nrows)
{
    extern __shared__ float smem[];
    float* xsm = smem;
    float* hsm = smem + 32 * 68;
    float* gs  = smem + 32 * 68 * 2;

    const int tid = threadIdx.x;
    const int r0  = blockIdx.x * 32;

    for (int i = tid; i < 32 * 64; i += 256) {
        int e = i >> 6, k = i & 63;
        int r = r0 + e;
        float xv = 0.f, hv = 0.f;
        if (r < nrows) {
            xv = x[(size_t)r * 64 + k];
            hv = h[(size_t)r * 64 + k];
            x[(size_t)r * 64 + k] = 0.0f;
        }
        xsm[e * 68 + k] = xv;
        hsm[e * 68 + k] = hv;
    }
    __syncthreads();

    const int warp = tid >> 5, lane = tid & 31;
    const bool is_gh = warp >= 4;
    const float* W   = is_gh ? whh : wih;
    const float* bb  = is_gh ? bhh : bih;
    const float* src = is_gh ? hsm : xsm;
    const int    off = is_gh ? 192 : 0;
    const int    jb  = (warp & 3) * 48;

    #pragma unroll
    for (int jc = 0; jc < 12; jc++) {
        const int j0 = jb + jc * 4;
        float a[4] = {0.f, 0.f, 0.f, 0.f};
        #pragma unroll
        for (int k = 0; k < 64; k += 4) {
            float4 xv = *(const float4*)(src + lane * 68 + k);
            #pragma unroll
            for (int jj = 0; jj < 4; jj++) {
                float4 wv = *(const float4*)(W + (size_t)(j0 + jj) * 64 + k);
                a[jj] += wv.x * xv.x + wv.y * xv.y + wv.z * xv.z + wv.w * xv.w;
            }
        }
        #pragma unroll
        for (int jj = 0; jj < 4; jj++)
            gs[lane * 384 + off + j0 + jj] = a[jj] + bb[j0 + jj];
    }
    __syncthreads();

    for (int i = tid; i < 32 * 64; i += 256) {
        int e = i >> 6, d = i & 63;
        int r = r0 + e;
        if (r >= nrows) continue;
        const float* g = gs + e * 384;
        float ir = g[d],       iz = g[64 + d],  in = g[128 + d];
        float hr = g[192 + d], hz = g[256 + d], hn = g[320 + d];
        float rr = 1.f / (1.f + expf(-(ir + hr)));
        float zz = 1.f / (1.f + expf(-(iz + hz)));
        float nn = tanhf(in + rr * hn);
        float hv = hsm[e * 68 + d];
        h[(size_t)r * 64 + d] = (1.f - zz) * nn + zz * hv;
    }
}

// ---------------- readout ----------------
__global__ __launch_bounds__(256) void readout_kernel(
    const float* __restrict__ h,
    const float* __restrict__ W1, const float* __restrict__ b1,
    const float* __restrict__ W2, const float* __restrict__ b2,
    const float* __restrict__ W3, const float* __restrict__ b3,
    float* __restrict__ out, int nrows)
{
    __shared__ float hs[32 * 68];
    __shared__ float l1s[32 * 132];
    __shared__ float l2s[32 * 132];
    __shared__ float lg[64];

    const int tid = threadIdx.x;
    const int r0  = blockIdx.x * 32;

    for (int i = tid; i < 32 * 64; i += 256) {
        int e = i >> 6, k = i & 63;
        int r = r0 + e;
        hs[e * 68 + k] = (r < nrows) ? h[(size_t)r * 64 + k] : 0.f;
    }
    __syncthreads();

    const int warp = tid >> 5, lane = tid & 31;
    #pragma unroll
    for (int jc = 0; jc < 4; jc++) {
        const int j0 = warp * 16 + jc * 4;
        float a[4] = {0.f, 0.f, 0.f, 0.f};
        #pragma unroll
        for (int k = 0; k < 64; k += 4) {
            float4 xv = *(const float4*)(hs + lane * 68 + k);
            #pragma unroll
            for (int jj = 0; jj < 4; jj++) {
                float4 wv = *(const float4*)(W1 + (size_t)(j0 + jj) * 64 + k);
                a[jj] += wv.x * xv.x + wv.y * xv.y + wv.z * xv.z + wv.w * xv.w;
            }
        }
        #pragma unroll
        for (int jj = 0; jj < 4; jj++)
            l1s[lane * 132 + j0 + jj] = fmaxf(a[jj] + b1[j0 + jj], 0.f);
    }
    __syncthreads();
    #pragma unroll
    for (int jc = 0; jc < 4; jc++) {
        const int j0 = warp * 16 + jc * 4;
        float a[4] = {0.f, 0.f, 0.f, 0.f};
        #pragma unroll 2
        for (int k = 0; k < 128; k += 4) {
            float4 xv = *(const float4*)(l1s + lane * 132 + k);
            #pragma unroll
            for (int jj = 0; jj < 4; jj++) {
                float4 wv = *(const float4*)(W2 + (size_t)(j0 + jj) * 128 + k);
                a[jj] += wv.x * xv.x + wv.y * xv.y + wv.z * xv.z + wv.w * xv.w;
            }
        }
        #pragma unroll
        for (int jj = 0; jj < 4; jj++)
            l2s[lane * 132 + j0 + jj] = fmaxf(a[jj] + b2[j0 + jj], 0.f);
    }
    __syncthreads();
    if (tid < 64) {
        int e = tid >> 1, j = tid & 1;
        float a = 0.f;
        #pragma unroll 4
        for (int k = 0; k < 128; k += 4) {
            float4 xv = *(const float4*)(l2s + e * 132 + k);
            float4 wv = *(const float4*)(W3 + (size_t)j * 128 + k);
            a += wv.x * xv.x + wv.y * xv.y + wv.z * xv.z + wv.w * xv.w;
        }
        lg[e * 2 + j] = a + b3[j];
    }
    __syncthreads();
    if (tid < 64) {
        int e = tid >> 1, j = tid & 1;
        int r = r0 + e;
        if (r < nrows) {
            float self  = lg[e * 2 + j];
            float other = lg[e * 2 + (j ^ 1)];
            out[(size_t)r * 2 + j] = 1.f / (1.f + expf(other - self));
        }
    }
}

extern "C" void kernel_launch(void* const* d_in, const int* in_sizes, int n_in,
                              void* d_out, int out_size)
{
    const int*   f2v_row  = (const int*)d_in[0];
    const int*   f2v_col  = (const int*)d_in[1];
    const int*   v2f_row  = (const int*)d_in[2];
    const int*   v2f_col  = (const int*)d_in[3];
    const float* f2v_feat = (const float*)d_in[4];
    const float* v2f_feat = (const float*)d_in[5];
    const float* f2v_w1 = (const float*)d_in[6];   const float* f2v_b1 = (const float*)d_in[7];
    const float* f2v_w2 = (const float*)d_in[8];   const float* f2v_b2 = (const float*)d_in[9];
    const float* f2v_w3 = (const float*)d_in[10];  const float* f2v_b3 = (const float*)d_in[11];
    const float* v2f_w1 = (const float*)d_in[12];  const float* v2f_b1 = (const float*)d_in[13];
    const float* v2f_w2 = (const float*)d_in[14];  const float* v2f_b2 = (const float*)d_in[15];
    const float* v2f_w3 = (const float*)d_in[16];  const float* v2f_b3 = (const float*)d_in[17];
    const float* gf_wih = (const float*)d_in[18];  const float* gf_whh = (const float*)d_in[19];
    const float* gf_bih = (const float*)d_in[20];  const float* gf_bhh = (const float*)d_in[21];
    const float* gv_wih = (const float*)d_in[22];  const float* gv_whh = (const float*)d_in[23];
    const float* gv_bih = (const float*)d_in[24];  const float* gv_bhh = (const float*)d_in[25];
    const float* ro_w1  = (const float*)d_in[26];  const float* ro_b1  = (const float*)d_in[27];
    const float* ro_w2  = (const float*)d_in[28];  const float* ro_b2  = (const float*)d_in[29];
    const float* ro_w3  = (const float*)d_in[30];  const float* ro_b3  = (const float*)d_in[31];
    float* out = (float*)d_out;

    float *var_h, *fac_h, *nm_var, *nm_fac;
    unsigned char *wp_f2v, *wp_v2f;
    cudaGetSymbolAddress((void**)&var_h,  g_var_h);
    cudaGetSymbolAddress((void**)&fac_h,  g_fac_h);
    cudaGetSymbolAddress((void**)&nm_var, g_nm_var);
    cudaGetSymbolAddress((void**)&nm_fac, g_nm_fac);
    cudaGetSymbolAddress((void**)&wp_f2v, g_wpack_f2v);
    cudaGetSymbolAddress((void**)&wp_v2f, g_wpack_v2f);

    cudaFuncSetAttribute(edge_mma_kernel, cudaFuncAttributeMaxDynamicSharedMemorySize, EDGE_SMEM_BYTES);
    cudaFuncSetAttribute(gru_kernel, cudaFuncAttributeMaxDynamicSharedMemorySize, GRU_SMEM_FLOATS * 4);

    pack_weights_kernel<<<32, 256>>>(wp_f2v,           f2v_w1, 128, 136);
    pack_weights_kernel<<<32, 256>>>(wp_f2v + 77824,   f2v_w2, 128, 128);
    pack_weights_kernel<<<32, 256>>>(wp_f2v + 155648,  f2v_w3,  64, 128);
    pack_weights_kernel<<<32, 256>>>(wp_v2f,           v2f_w1, 128, 136);
    pack_weights_kernel<<<32, 256>>>(wp_v2f + 77824,   v2f_w2, 128, 128);
    pack_weights_kernel<<<32, 256>>>(wp_v2f + 155648,  v2f_w3,  64, 128);

    zero_kernel<<<256, 256>>>(var_h, NV * 64);
    zero_kernel<<<512, 256>>>(fac_h, NF * 64);
    zero_kernel<<<256, 256>>>(nm_var, NV * 64);
    zero_kernel<<<512, 256>>>(nm_fac, NF * 64);

    for (int s = 0; s < 5; s++) {
        edge_mma_kernel<<<NE / 128, 512, EDGE_SMEM_BYTES>>>(
            fac_h, var_h, f2v_row, f2v_col, f2v_feat, wp_f2v,
            f2v_b1, f2v_b2, f2v_b3, nm_var);
        gru_kernel<<<(NV + 31) / 32, 256, GRU_SMEM_FLOATS * 4>>>(
            var_h, nm_var, gf_wih, gf_whh, gf_bih, gf_bhh, NV);

        edge_mma_kernel<<<NE / 128, 512, EDGE_SMEM_BYTES>>>(
            var_h, fac_h, v2f_row, v2f_col, v2f_feat, wp_v2f,
            v2f_b1, v2f_b2, v2f_b3, nm_fac);
        gru_kernel<<<NF / 32, 256, GRU_SMEM_FLOATS * 4>>>(
            fac_h, nm_fac, gv_wih, gv_whh, gv_bih, gv_bhh, NF);
    }

    readout_kernel<<<(NV + 31) / 32, 256>>>(
        var_h, ro_w1, ro_b1, ro_w2, ro_b2, ro_w3, ro_b3, out, NV);
}

// round 6
// speedup vs baseline: 3.9519x; 1.7248x over previous
#include <cuda_runtime.h>
#include <cuda_bf16.h>
#include <cstdint>
#include <math.h>

#define NV 10000
#define NF 80000
#define NE 160000

// ---------------- edge-tile geometry (row stride 304 B = 19*16, LDSM conflict-free)
#define RSTRIDE 304
#define A_LO_OFF 38912          // 128 rows * 304
#define W1_PLANE 38912
#define W3_PLANE 19456

// ---------------- GRU-tile geometry (row stride 272 B = 17*16, conflict-free)
#define GR 272
#define GA_LO 34816             // 128 rows * 272
#define GW_LO 69632             // 256 rows * 272 (hi plane size)

// ---------------- persistent scratch ----------------
__device__ float g_var_h[NV * 64];
__device__ float g_fac_h[NF * 64];
__device__ float g_nm_var[NV * 64];
__device__ float g_nm_fac[NF * 64];
__device__ __align__(256) unsigned char g_wpack_f2v[194560];
__device__ __align__(256) unsigned char g_wpack_v2f[194560];
__device__ __align__(256) unsigned char g_wgru_gf[139264];   // 256x136 bf16 hi+lo
__device__ __align__(256) unsigned char g_wgru_gv[139264];

// ---------------- PTX helpers (sm_90 baseline; NO tcgen05) ----------------
__device__ __forceinline__ uint32_t smem_u32(const void* p) {
    uint32_t a;
    asm("{ .reg .u64 t; cvta.to.shared.u64 t, %1; cvt.u32.u64 %0, t; }" : "=r"(a) : "l"(p));
    return a;
}
#define MBARRIER_INIT(mbar, cnt) \
    asm volatile("mbarrier.init.shared.b64 [%0], %1;" :: "r"(mbar), "r"(cnt) : "memory")
#define MBARRIER_EXPECT_TX(mbar, bytes) \
    asm volatile("mbarrier.arrive.expect_tx.shared.b64 _, [%0], %1;" :: "r"(mbar), "r"(bytes) : "memory")
#define MBARRIER_WAIT_PARITY(mbar, ph) do { \
    asm volatile("{\n\t.reg .pred P1;\n\t" \
        "W_%=:\n\tmbarrier.try_wait.parity.acquire.cta.shared::cta.b64 P1, [%0], %1, 0x989680;\n\t" \
        "@P1 bra.uni D_%=;\n\tbra.uni W_%=;\n\tD_%=:\n\t}" \
        :: "r"(mbar), "r"(ph) : "memory"); \
} while (0)

__device__ __forceinline__ void bulk_copy_g2s(uint32_t dst, const void* src,
                                              uint32_t bytes, uint32_t mbar) {
    asm volatile(
        "cp.async.bulk.shared::cluster.global.mbarrier::complete_tx::bytes [%0], [%1], %2, [%3];"
        :: "r"(dst), "l"(src), "r"(bytes), "r"(mbar) : "memory");
}
__device__ __forceinline__ void ldsm4(uint32_t addr, uint32_t* r) {
    asm volatile("ldmatrix.sync.aligned.m8n8.x4.shared.b16 {%0,%1,%2,%3}, [%4];"
        : "=r"(r[0]), "=r"(r[1]), "=r"(r[2]), "=r"(r[3]) : "r"(addr));
}
__device__ __forceinline__ void mma16816(float* d, const uint32_t* a, const uint32_t* b) {
    asm volatile("mma.sync.aligned.m16n8k16.row.col.f32.bf16.bf16.f32 "
        "{%0,%1,%2,%3}, {%4,%5,%6,%7}, {%8,%9}, {%0,%1,%2,%3};"
        : "+f"(d[0]), "+f"(d[1]), "+f"(d[2]), "+f"(d[3])
        : "r"(a[0]), "r"(a[1]), "r"(a[2]), "r"(a[3]), "r"(b[0]), "r"(b[1]));
}

// ---------------- zero ----------------
__global__ void zero_kernel(float* __restrict__ p, int n) {
    int i = blockIdx.x * blockDim.x + threadIdx.x;
    for (; i < n; i += gridDim.x * blockDim.x) p[i] = 0.0f;
}

// ---------------- edge weight pre-pack ----------------
__global__ void pack_weights_kernel(unsigned char* __restrict__ dst,
                                    const float* __restrict__ W,
                                    int nrows, int kin) {
    const int total = nrows * 152;
    const int plane = nrows * RSTRIDE;
    for (int i = blockIdx.x * blockDim.x + threadIdx.x; i < total;
         i += gridDim.x * blockDim.x) {
        int n = i / 152, k = i - n * 152;
        float v = (k < kin) ? W[n * kin + k] : 0.0f;
        __nv_bfloat16 hi = __float2bfloat16(v);
        __nv_bfloat16 lo = __float2bfloat16(v - __bfloat162float(hi));
        uint32_t off = (uint32_t)n * RSTRIDE + (uint32_t)k * 2;
        *(__nv_bfloat16*)(dst + off) = hi;
        *(__nv_bfloat16*)(dst + plane + off) = lo;
    }
}

// ---------------- GRU weight pre-pack: W' = [wr|hr; wz|hz; wn|0; 0|hn] ------
__global__ void pack_gru_kernel(unsigned char* __restrict__ dst,
                                const float* __restrict__ wih,
                                const float* __restrict__ whh) {
    const int total = 256 * 136;
    for (int i = blockIdx.x * blockDim.x + threadIdx.x; i < total;
         i += gridDim.x * blockDim.x) {
        int r = i / 136, k = i - r * 136;
        float v = 0.0f;
        if (k < 128) {
            if (r < 128)       v = (k < 64) ? wih[r * 64 + k] : whh[r * 64 + (k - 64)];
            else if (r < 192)  { if (k < 64)  v = wih[(r + 0) * 64 + k]; }          // rows 128..191 = wih_n
            else               { if (k >= 64) v = whh[(r - 64) * 64 + (k - 64)]; }  // rows 192..255 -> whh rows 128..191
        }
        __nv_bfloat16 hi = __float2bfloat16(v);
        __nv_bfloat16 lo = __float2bfloat16(v - __bfloat162float(hi));
        uint32_t off = (uint32_t)r * GR + (uint32_t)k * 2;
        *(__nv_bfloat16*)(dst + off) = hi;
        *(__nv_bfloat16*)(dst + GW_LO + off) = lo;
    }
}

// ---------------- generic HMMA tile: [128 x K] x [N x K]^T ------------------
template<int KCH, int NPAIR>
__device__ __forceinline__ void layer_mma_s(
    uint32_t aA, uint32_t aW, uint32_t rstr, uint32_t aLo, uint32_t wLo,
    int lane, int mbase, int nbase, float* acc)
{
    const uint32_t aRow = aA + (uint32_t)(mbase + (lane & 15)) * rstr + ((lane >> 4) << 4);
    const uint32_t bRow = aW + (uint32_t)(nbase + (lane & 7) + ((lane >> 4) << 3)) * rstr
                        + (((lane >> 3) & 1) << 4);
    #pragma unroll
    for (int kc = 0; kc < KCH; kc++) {
        uint32_t ah[8], al[8];
        ldsm4(aRow + kc * 32, ah);
        ldsm4(aRow + 16 * rstr + kc * 32, ah + 4);
        ldsm4(aRow + aLo + kc * 32, al);
        ldsm4(aRow + aLo + 16 * rstr + kc * 32, al + 4);
        #pragma unroll
        for (int np = 0; np < NPAIR; np++) {
            uint32_t bh[4], bl[4];
            ldsm4(bRow + np * 16 * rstr + kc * 32, bh);
            ldsm4(bRow + wLo + np * 16 * rstr + kc * 32, bl);
            #pragma unroll
            for (int m = 0; m < 2; m++) {
                #pragma unroll
                for (int h = 0; h < 2; h++) {
                    float* d = acc + ((m * NPAIR + np) * 2 + h) * 4;
                    mma16816(d, ah + m * 4, bh + h * 2);
                    mma16816(d, ah + m * 4, bl + h * 2);
                    mma16816(d, al + m * 4, bh + h * 2);
                }
            }
        }
    }
}

// epilogue edge layers 1/2: +bias, relu, hi/lo split, write back into A tile
__device__ __forceinline__ void epi12(unsigned char* Ab, const float* bias,
                                      int lane, int mbase, int nbase, const float* acc)
{
    #pragma unroll
    for (int m = 0; m < 2; m++)
        #pragma unroll
        for (int np = 0; np < 2; np++)
            #pragma unroll
            for (int h = 0; h < 2; h++) {
                const float* d = acc + ((m * 2 + np) * 2 + h) * 4;
                int c = nbase + np * 16 + h * 8 + 2 * (lane & 3);
                int r = mbase + m * 16 + (lane >> 2);
                float b0 = bias[c], b1 = bias[c + 1];
                float v0 = fmaxf(d[0] + b0, 0.f), v1 = fmaxf(d[1] + b1, 0.f);
                float v2 = fmaxf(d[2] + b0, 0.f), v3 = fmaxf(d[3] + b1, 0.f);
                __nv_bfloat162 hA = __floats2bfloat162_rn(v0, v1);
                __nv_bfloat162 lA = __floats2bfloat162_rn(v0 - __low2float(hA),
                                                          v1 - __high2float(hA));
                __nv_bfloat162 hB = __floats2bfloat162_rn(v2, v3);
                __nv_bfloat162 lB = __floats2bfloat162_rn(v2 - __low2float(hB),
                                                          v3 - __high2float(hB));
                uint32_t o0 = (uint32_t)r * RSTRIDE + (uint32_t)c * 2;
                uint32_t o1 = o0 + 8u * RSTRIDE;
                *(uint32_t*)(Ab + o0)            = *(uint32_t*)&hA;
                *(uint32_t*)(Ab + A_LO_OFF + o0) = *(uint32_t*)&lA;
                *(uint32_t*)(Ab + o1)            = *(uint32_t*)&hB;
                *(uint32_t*)(Ab + A_LO_OFF + o1) = *(uint32_t*)&lB;
            }
}

// ---------------- fused edge MLP: 136->128->128->64 on HMMA ----------------
#define SM_W    77824
#define SM_RS   155648
#define SM_CS   156160
#define SM_BIAS 156672
#define SM_MBW  157952
#define EDGE_SMEM_BYTES 157984
__global__ __launch_bounds__(512, 1) void edge_mma_kernel(
    const float* __restrict__ Ah, const float* __restrict__ Bh,
    const int* __restrict__ rowi, const int* __restrict__ coli,
    const float* __restrict__ feat,
    const unsigned char* __restrict__ wsrc,
    const float* __restrict__ b1, const float* __restrict__ b2,
    const float* __restrict__ b3,
    float* __restrict__ nm)
{
    extern __shared__ __align__(256) unsigned char sm[];
    const uint32_t smb = smem_u32(sm);
    const int tid = threadIdx.x;
    const int e0 = blockIdx.x * 128;

    int*   rs     = (int*)(sm + SM_RS);
    int*   cs     = (int*)(sm + SM_CS);
    float* bias_s = (float*)(sm + SM_BIAS);
    const uint32_t mbw = smb + SM_MBW;

    if (tid == 0) MBARRIER_INIT(mbw, 1u);
    __syncthreads();
    if (tid == 0) {
        MBARRIER_EXPECT_TX(mbw, 77824u);
        bulk_copy_g2s(smb + SM_W, wsrc, 77824u, mbw);
    }
    if (tid < 128)       rs[tid] = rowi[e0 + tid];
    else if (tid < 256)  cs[tid - 128] = coli[e0 + tid - 128];
    for (int i = tid; i < 320; i += 512)
        bias_s[i] = (i < 128) ? b1[i] : (i < 256 ? b2[i - 128] : b3[i - 256]);
    __syncthreads();

    for (int i = tid; i < 128 * 38; i += 512) {
        int e = i / 38, q = i - e * 38;
        float4 x;
        if (q < 16)       x = *(const float4*)(Ah + (size_t)rs[e] * 64 + q * 4);
        else if (q < 32)  x = *(const float4*)(Bh + (size_t)cs[e] * 64 + (q - 16) * 4);
        else if (q == 32) x = *(const float4*)(feat + (size_t)rs[e] * 4);
        else if (q == 33) x = *(const float4*)(feat + (size_t)cs[e] * 4);
        else              x = make_float4(0.f, 0.f, 0.f, 0.f);
        __nv_bfloat162 h01 = __floats2bfloat162_rn(x.x, x.y);
        __nv_bfloat162 h23 = __floats2bfloat162_rn(x.z, x.w);
        __nv_bfloat162 l01 = __floats2bfloat162_rn(x.x - __low2float(h01), x.y - __high2float(h01));
        __nv_bfloat162 l23 = __floats2bfloat162_rn(x.z - __low2float(h23), x.w - __high2float(h23));
        uint32_t off = (uint32_t)e * RSTRIDE + (uint32_t)q * 8;
        *(uint2*)(sm + off)            = make_uint2(*(uint32_t*)&h01, *(uint32_t*)&h23);
        *(uint2*)(sm + A_LO_OFF + off) = make_uint2(*(uint32_t*)&l01, *(uint32_t*)&l23);
    }
    __syncthreads();

    const int w = tid >> 5, lane = tid & 31;
    const int mbase = (w & 3) * 32;
    const int nb32  = (w >> 2) * 32;
    float acc[32];

    MBARRIER_WAIT_PARITY(mbw, 0);
    #pragma unroll
    for (int i = 0; i < 32; i++) acc[i] = 0.f;
    layer_mma_s<9, 2>(smb, smb + SM_W, RSTRIDE, A_LO_OFF, W1_PLANE, lane, mbase, nb32, acc);
    __syncthreads();
    if (tid == 0) {
        MBARRIER_EXPECT_TX(mbw, 77824u);
        bulk_copy_g2s(smb + SM_W, wsrc + 77824, 77824u, mbw);
    }
    epi12(sm, bias_s, lane, mbase, nb32, acc);
    __syncthreads();

    MBARRIER_WAIT_PARITY(mbw, 1);
    #pragma unroll
    for (int i = 0; i < 32; i++) acc[i] = 0.f;
    layer_mma_s<8, 2>(smb, smb + SM_W, RSTRIDE, A_LO_OFF, W1_PLANE, lane, mbase, nb32, acc);
    __syncthreads();
    if (tid == 0) {
        MBARRIER_EXPECT_TX(mbw, 38912u);
        bulk_copy_g2s(smb + SM_W, wsrc + 155648, 38912u, mbw);
    }
    epi12(sm, bias_s + 128, lane, mbase, nb32, acc);
    __syncthreads();

    MBARRIER_WAIT_PARITY(mbw, 0);
    #pragma unroll
    for (int i = 0; i < 16; i++) acc[i] = 0.f;
    const int nb16 = (w >> 2) * 16;
    layer_mma_s<8, 1>(smb, smb + SM_W, RSTRIDE, A_LO_OFF, W3_PLANE, lane, mbase, nb16, acc);

    #pragma unroll
    for (int m = 0; m < 2; m++)
        #pragma unroll
        for (int h = 0; h < 2; h++) {
            const float* d = acc + (m * 2 + h) * 4;
            int c = nb16 + h * 8 + 2 * (lane & 3);
            int r = mbase + m * 16 + (lane >> 2);
            float b0 = bias_s[256 + c], b1v = bias_s[256 + c + 1];
            float* p0 = nm + (size_t)cs[r] * 64 + c;
            float* p1 = nm + (size_t)cs[r + 8] * 64 + c;
            atomicAdd(p0,     d[0] + b0);
            atomicAdd(p0 + 1, d[1] + b1v);
            atomicAdd(p1,     d[2] + b0);
            atomicAdd(p1 + 1, d[3] + b1v);
        }
}

// ---------------- HMMA GRU: [x|h](128x128) @ W'(256x128)^T ------------------
// smem: A hi[34816] lo[34816] | W hi[69632] lo[69632] (reused as gs f32 128x256)
//       | bias[1024] | mbar
#define GSM_W    69632
#define GSM_BIAS 208896
#define GSM_MBW  209920
#define GRU_SMEM_BYTES 209952
__global__ __launch_bounds__(512, 1) void gru_mma_kernel(
    float* __restrict__ h, float* __restrict__ x,
    const unsigned char* __restrict__ wsrc,
    const float* __restrict__ bih, const float* __restrict__ bhh,
    int nrows)
{
    extern __shared__ __align__(256) unsigned char sm[];
    const uint32_t smb = smem_u32(sm);
    const int tid = threadIdx.x;
    const int r0 = blockIdx.x * 128;

    float* bias_s = (float*)(sm + GSM_BIAS);   // [0:128)=br,bz  [128:192)=bin  [192:256)=bhn
    float* gs     = (float*)(sm + GSM_W);      // f32 [128][256], overlays W after MMA
    const uint32_t mbw = smb + GSM_MBW;

    if (tid == 0) MBARRIER_INIT(mbw, 1u);
    __syncthreads();
    if (tid == 0) {
        MBARRIER_EXPECT_TX(mbw, 139264u);
        bulk_copy_g2s(smb + GSM_W, wsrc, 139264u, mbw);
    }
    for (int i = tid; i < 256; i += 512) {
        float v;
        if (i < 128)      v = bih[i] + bhh[i];
        else if (i < 192) v = bih[i];             // bin[j] = bih[128+j]
        else              v = bhh[i - 64];        // bhn[j] = bhh[128+j]
        bias_s[i] = v;
    }

    // gather A = [x | h] per row, hi/lo split; zero x after reading
    for (int i = tid; i < 128 * 32; i += 512) {
        int e = i >> 5, q = i & 31;
        int rr = r0 + e;
        int rc = rr < nrows ? rr : nrows - 1;
        float4 xv;
        if (q < 16) {
            xv = *(const float4*)(x + (size_t)rc * 64 + q * 4);
            if (rr < nrows) *(float4*)(x + (size_t)rc * 64 + q * 4) = make_float4(0.f, 0.f, 0.f, 0.f);
        } else {
            xv = *(const float4*)(h + (size_t)rc * 64 + (q - 16) * 4);
        }
        __nv_bfloat162 h01 = __floats2bfloat162_rn(xv.x, xv.y);
        __nv_bfloat162 h23 = __floats2bfloat162_rn(xv.z, xv.w);
        __nv_bfloat162 l01 = __floats2bfloat162_rn(xv.x - __low2float(h01), xv.y - __high2float(h01));
        __nv_bfloat162 l23 = __floats2bfloat162_rn(xv.z - __low2float(h23), xv.w - __high2float(h23));
        uint32_t off = (uint32_t)e * GR + (uint32_t)q * 8;
        *(uint2*)(sm + off)         = make_uint2(*(uint32_t*)&h01, *(uint32_t*)&h23);
        *(uint2*)(sm + GA_LO + off) = make_uint2(*(uint32_t*)&l01, *(uint32_t*)&l23);
    }
    __syncthreads();

    const int w = tid >> 5, lane = tid & 31;
    const int mbase = (w & 3) * 32;
    const int nbase = (w >> 2) * 64;
    float acc[64];
    #pragma unroll
    for (int i = 0; i < 64; i++) acc[i] = 0.f;

    MBARRIER_WAIT_PARITY(mbw, 0);
    layer_mma_s<8, 4>(smb, smb + GSM_W, GR, GA_LO, GW_LO, lane, mbase, nbase, acc);
    __syncthreads();   // all W reads done; gs may overwrite W region

    #pragma unroll
    for (int m = 0; m < 2; m++)
        #pragma unroll
        for (int np = 0; np < 4; np++)
            #pragma unroll
            for (int hh = 0; hh < 2; hh++) {
                const float* d = acc + ((m * 4 + np) * 2 + hh) * 4;
                int c = nbase + np * 16 + hh * 8 + 2 * (lane & 3);
                int r = mbase + m * 16 + (lane >> 2);
                gs[r * 256 + c]           = d[0];
                gs[r * 256 + c + 1]       = d[1];
                gs[(r + 8) * 256 + c]     = d[2];
                gs[(r + 8) * 256 + c + 1] = d[3];
            }
    __syncthreads();

    // elementwise gate math
    for (int i = tid; i < 128 * 64; i += 512) {
        int e = i >> 6, d = i & 63;
        int r = r0 + e;
        if (r >= nrows) continue;
        const float* g = gs + e * 256;
        float pr = g[d]       + bias_s[d];
        float pz = g[64 + d]  + bias_s[64 + d];
        float in = g[128 + d] + bias_s[128 + d];
        float hn = g[192 + d] + bias_s[192 + d];
        float rr = 1.f / (1.f + expf(-pr));
        float zz = 1.f / (1.f + expf(-pz));
        float nn = tanhf(in + rr * hn);
        float hv = h[(size_t)r * 64 + d];
        h[(size_t)r * 64 + d] = (1.f - zz) * nn + zz * hv;
    }
}

// ---------------- readout ----------------
__global__ __launch_bounds__(256) void readout_kernel(
    const float* __restrict__ h,
    const float* __restrict__ W1, const float* __restrict__ b1,
    const float* __restrict__ W2, const float* __restrict__ b2,
    const float* __restrict__ W3, const float* __restrict__ b3,
    float* __restrict__ out, int nrows)
{
    __shared__ float hs[32 * 68];
    __shared__ float l1s[32 * 132];
    __shared__ float l2s[32 * 132];
    __shared__ float lg[64];

    const int tid = threadIdx.x;
    const int r0  = blockIdx.x * 32;

    for (int i = tid; i < 32 * 64; i += 256) {
        int e = i >> 6, k = i & 63;
        int r = r0 + e;
        hs[e * 68 + k] = (r < nrows) ? h[(size_t)r * 64 + k] : 0.f;
    }
    __syncthreads();

    const int warp = tid >> 5, lane = tid & 31;
    #pragma unroll
    for (int jc = 0; jc < 4; jc++) {
        const int j0 = warp * 16 + jc * 4;
        float a[4] = {0.f, 0.f, 0.f, 0.f};
        #pragma unroll
        for (int k = 0; k < 64; k += 4) {
            float4 xv = *(const float4*)(hs + lane * 68 + k);
            #pragma unroll
            for (int jj = 0; jj < 4; jj++) {
                float4 wv = *(const float4*)(W1 + (size_t)(j0 + jj) * 64 + k);
                a[jj] += wv.x * xv.x + wv.y * xv.y + wv.z * xv.z + wv.w * xv.w;
            }
        }
        #pragma unroll
        for (int jj = 0; jj < 4; jj++)
            l1s[lane * 132 + j0 + jj] = fmaxf(a[jj] + b1[j0 + jj], 0.f);
    }
    __syncthreads();
    #pragma unroll
    for (int jc = 0; jc < 4; jc++) {
        const int j0 = warp * 16 + jc * 4;
        float a[4] = {0.f, 0.f, 0.f, 0.f};
        #pragma unroll 2
        for (int k = 0; k < 128; k += 4) {
            float4 xv = *(const float4*)(l1s + lane * 132 + k);
            #pragma unroll
            for (int jj = 0; jj < 4; jj++) {
                float4 wv = *(const float4*)(W2 + (size_t)(j0 + jj) * 128 + k);
                a[jj] += wv.x * xv.x + wv.y * xv.y + wv.z * xv.z + wv.w * xv.w;
            }
        }
        #pragma unroll
        for (int jj = 0; jj < 4; jj++)
            l2s[lane * 132 + j0 + jj] = fmaxf(a[jj] + b2[j0 + jj], 0.f);
    }
    __syncthreads();
    if (tid < 64) {
        int e = tid >> 1, j = tid & 1;
        float a = 0.f;
        #pragma unroll 4
        for (int k = 0; k < 128; k += 4) {
            float4 xv = *(const float4*)(l2s + e * 132 + k);
            float4 wv = *(const float4*)(W3 + (size_t)j * 128 + k);
            a += wv.x * xv.x + wv.y * xv.y + wv.z * xv.z + wv.w * xv.w;
        }
        lg[e * 2 + j] = a + b3[j];
    }
    __syncthreads();
    if (tid < 64) {
        int e = tid >> 1, j = tid & 1;
        int r = r0 + e;
        if (r < nrows) {
            float self  = lg[e * 2 + j];
            float other = lg[e * 2 + (j ^ 1)];
            out[(size_t)r * 2 + j] = 1.f / (1.f + expf(other - self));
        }
    }
}

extern "C" void kernel_launch(void* const* d_in, const int* in_sizes, int n_in,
                              void* d_out, int out_size)
{
    const int*   f2v_row  = (const int*)d_in[0];
    const int*   f2v_col  = (const int*)d_in[1];
    const int*   v2f_row  = (const int*)d_in[2];
    const int*   v2f_col  = (const int*)d_in[3];
    const float* f2v_feat = (const float*)d_in[4];
    const float* v2f_feat = (const float*)d_in[5];
    const float* f2v_w1 = (const float*)d_in[6];   const float* f2v_b1 = (const float*)d_in[7];
    const float* f2v_w2 = (const float*)d_in[8];   const float* f2v_b2 = (const float*)d_in[9];
    const float* f2v_w3 = (const float*)d_in[10];  const float* f2v_b3 = (const float*)d_in[11];
    const float* v2f_w1 = (const float*)d_in[12];  const float* v2f_b1 = (const float*)d_in[13];
    const float* v2f_w2 = (const float*)d_in[14];  const float* v2f_b2 = (const float*)d_in[15];
    const float* v2f_w3 = (const float*)d_in[16];  const float* v2f_b3 = (const float*)d_in[17];
    const float* gf_wih = (const float*)d_in[18];  const float* gf_whh = (const float*)d_in[19];
    const float* gf_bih = (const float*)d_in[20];  const float* gf_bhh = (const float*)d_in[21];
    const float* gv_wih = (const float*)d_in[22];  const float* gv_whh = (const float*)d_in[23];
    const float* gv_bih = (const float*)d_in[24];  const float* gv_bhh = (const float*)d_in[25];
    const float* ro_w1  = (const float*)d_in[26];  const float* ro_b1  = (const float*)d_in[27];
    const float* ro_w2  = (const float*)d_in[28];  const float* ro_b2  = (const float*)d_in[29];
    const float* ro_w3  = (const float*)d_in[30];  const float* ro_b3  = (const float*)d_in[31];
    float* out = (float*)d_out;

    float *var_h, *fac_h, *nm_var, *nm_fac;
    unsigned char *wp_f2v, *wp_v2f, *wg_gf, *wg_gv;
    cudaGetSymbolAddress((void**)&var_h,  g_var_h);
    cudaGetSymbolAddress((void**)&fac_h,  g_fac_h);
    cudaGetSymbolAddress((void**)&nm_var, g_nm_var);
    cudaGetSymbolAddress((void**)&nm_fac, g_nm_fac);
    cudaGetSymbolAddress((void**)&wp_f2v, g_wpack_f2v);
    cudaGetSymbolAddress((void**)&wp_v2f, g_wpack_v2f);
    cudaGetSymbolAddress((void**)&wg_gf,  g_wgru_gf);
    cudaGetSymbolAddress((void**)&wg_gv,  g_wgru_gv);

    cudaFuncSetAttribute(edge_mma_kernel, cudaFuncAttributeMaxDynamicSharedMemorySize, EDGE_SMEM_BYTES);
    cudaFuncSetAttribute(gru_mma_kernel,  cudaFuncAttributeMaxDynamicSharedMemorySize, GRU_SMEM_BYTES);

    pack_weights_kernel<<<32, 256>>>(wp_f2v,           f2v_w1, 128, 136);
    pack_weights_kernel<<<32, 256>>>(wp_f2v + 77824,   f2v_w2, 128, 128);
    pack_weights_kernel<<<32, 256>>>(wp_f2v + 155648,  f2v_w3,  64, 128);
    pack_weights_kernel<<<32, 256>>>(wp_v2f,           v2f_w1, 128, 136);
    pack_weights_kernel<<<32, 256>>>(wp_v2f + 77824,   v2f_w2, 128, 128);
    pack_weights_kernel<<<32, 256>>>(wp_v2f + 155648,  v2f_w3,  64, 128);
    pack_gru_kernel<<<32, 256>>>(wg_gf, gf_wih, gf_whh);
    pack_gru_kernel<<<32, 256>>>(wg_gv, gv_wih, gv_whh);

    zero_kernel<<<256, 256>>>(var_h, NV * 64);
    zero_kernel<<<512, 256>>>(fac_h, NF * 64);
    zero_kernel<<<256, 256>>>(nm_var, NV * 64);
    zero_kernel<<<512, 256>>>(nm_fac, NF * 64);

    for (int s = 0; s < 5; s++) {
        edge_mma_kernel<<<NE / 128, 512, EDGE_SMEM_BYTES>>>(
            fac_h, var_h, f2v_row, f2v_col, f2v_feat, wp_f2v,
            f2v_b1, f2v_b2, f2v_b3, nm_var);
        gru_mma_kernel<<<(NV + 127) / 128, 512, GRU_SMEM_BYTES>>>(
            var_h, nm_var, wg_gf, gf_bih, gf_bhh, NV);

        edge_mma_kernel<<<NE / 128, 512, EDGE_SMEM_BYTES>>>(
            var_h, fac_h, v2f_row, v2f_col, v2f_feat, wp_v2f,
            v2f_b1, v2f_b2, v2f_b3, nm_fac);
        gru_mma_kernel<<<NF / 128, 512, GRU_SMEM_BYTES>>>(
            fac_h, nm_fac, wg_gv, gv_bih, gv_bhh, NF);
    }

    readout_kernel<<<(NV + 31) / 32, 256>>>(
        var_h, ro_w1, ro_b1, ro_w2, ro_b2, ro_w3, ro_b3, out, NV);
}

// round 7
// speedup vs baseline: 4.4149x; 1.1172x over previous
#include <cuda_runtime.h>
#include <cuda_bf16.h>
#include <cstdint>
#include <math.h>

#define NV 10000
#define NF 80000
#define NE 160000

// ---------------- edge-tile geometry: row stride 272 B (17*16, conflict-free)
#define ER 272
#define EA_LO 17408             // 64 rows * 272
#define EW_LO128 34816          // lo-plane offset for 128-row W
#define EW_LO64  17408          // lo-plane offset for 64-row W

// ---------------- GRU-tile geometry (row stride 272)
#define GR 272
#define GA_LO 34816             // 128 rows * 272
#define GW_LO 69632             // 256 rows * 272

// ---------------- persistent scratch ----------------
__device__ float g_var_h[NV * 64];
__device__ float g_fac_h[NF * 64];
__device__ float g_nm_var[NV * 64];
__device__ float g_nm_fac[NF * 64];
// per direction: W1 hi+lo 69632 | W2 hi+lo 69632 | W3 hi+lo 34816 = 174080
__device__ __align__(256) unsigned char g_wpack_f2v[174080];
__device__ __align__(256) unsigned char g_wpack_v2f[174080];
__device__ __align__(256) unsigned char g_wgru_gf[139264];   // 256x136 bf16 hi+lo
__device__ __align__(256) unsigned char g_wgru_gv[139264];

// ---------------- PTX helpers (sm_90 baseline; NO tcgen05) ----------------
__device__ __forceinline__ uint32_t smem_u32(const void* p) {
    uint32_t a;
    asm("{ .reg .u64 t; cvta.to.shared.u64 t, %1; cvt.u32.u64 %0, t; }" : "=r"(a) : "l"(p));
    return a;
}
#define MBARRIER_INIT(mbar, cnt) \
    asm volatile("mbarrier.init.shared.b64 [%0], %1;" :: "r"(mbar), "r"(cnt) : "memory")
#define MBARRIER_EXPECT_TX(mbar, bytes) \
    asm volatile("mbarrier.arrive.expect_tx.shared.b64 _, [%0], %1;" :: "r"(mbar), "r"(bytes) : "memory")
#define MBARRIER_WAIT_PARITY(mbar, ph) do { \
    asm volatile("{\n\t.reg .pred P1;\n\t" \
        "W_%=:\n\tmbarrier.try_wait.parity.acquire.cta.shared::cta.b64 P1, [%0], %1, 0x989680;\n\t" \
        "@P1 bra.uni D_%=;\n\tbra.uni W_%=;\n\tD_%=:\n\t}" \
        :: "r"(mbar), "r"(ph) : "memory"); \
} while (0)

__device__ __forceinline__ void bulk_copy_g2s(uint32_t dst, const void* src,
                                              uint32_t bytes, uint32_t mbar) {
    asm volatile(
        "cp.async.bulk.shared::cluster.global.mbarrier::complete_tx::bytes [%0], [%1], %2, [%3];"
        :: "r"(dst), "l"(src), "r"(bytes), "r"(mbar) : "memory");
}
__device__ __forceinline__ void ldsm4(uint32_t addr, uint32_t* r) {
    asm volatile("ldmatrix.sync.aligned.m8n8.x4.shared.b16 {%0,%1,%2,%3}, [%4];"
        : "=r"(r[0]), "=r"(r[1]), "=r"(r[2]), "=r"(r[3]) : "r"(addr));
}
__device__ __forceinline__ void mma16816(float* d, const uint32_t* a, const uint32_t* b) {
    asm volatile("mma.sync.aligned.m16n8k16.row.col.f32.bf16.bf16.f32 "
        "{%0,%1,%2,%3}, {%4,%5,%6,%7}, {%8,%9}, {%0,%1,%2,%3};"
        : "+f"(d[0]), "+f"(d[1]), "+f"(d[2]), "+f"(d[3])
        : "r"(a[0]), "r"(a[1]), "r"(a[2]), "r"(a[3]), "r"(b[0]), "r"(b[1]));
}
__device__ __forceinline__ void mma16808(float* d, const uint32_t* a, uint32_t b) {
    asm volatile("mma.sync.aligned.m16n8k8.row.col.f32.bf16.bf16.f32 "
        "{%0,%1,%2,%3}, {%4,%5}, {%6}, {%0,%1,%2,%3};"
        : "+f"(d[0]), "+f"(d[1]), "+f"(d[2]), "+f"(d[3])
        : "r"(a[0]), "r"(a[1]), "r"(b));
}

// ---------------- zero ----------------
__global__ void zero_kernel(float* __restrict__ p, int n) {
    int i = blockIdx.x * blockDim.x + threadIdx.x;
    for (; i < n; i += gridDim.x * blockDim.x) p[i] = 0.0f;
}

// ---------------- edge weight pre-pack: rows of 136 elems (272 B) ----------
__global__ void pack_weights_kernel(unsigned char* __restrict__ dst,
                                    const float* __restrict__ W,
                                    int nrows, int kin) {
    const int total = nrows * 136;
    const int plane = nrows * ER;
    for (int i = blockIdx.x * blockDim.x + threadIdx.x; i < total;
         i += gridDim.x * blockDim.x) {
        int n = i / 136, k = i - n * 136;
        float v = (k < kin) ? W[n * kin + k] : 0.0f;
        __nv_bfloat16 hi = __float2bfloat16(v);
        __nv_bfloat16 lo = __float2bfloat16(v - __bfloat162float(hi));
        uint32_t off = (uint32_t)n * ER + (uint32_t)k * 2;
        *(__nv_bfloat16*)(dst + off) = hi;
        *(__nv_bfloat16*)(dst + plane + off) = lo;
    }
}

// ---------------- GRU weight pre-pack: W' = [wr|hr; wz|hz; wn|0; 0|hn] ------
__global__ void pack_gru_kernel(unsigned char* __restrict__ dst,
                                const float* __restrict__ wih,
                                const float* __restrict__ whh) {
    const int total = 256 * 136;
    for (int i = blockIdx.x * blockDim.x + threadIdx.x; i < total;
         i += gridDim.x * blockDim.x) {
        int r = i / 136, k = i - r * 136;
        float v = 0.0f;
        if (k < 128) {
            if (r < 128)       v = (k < 64) ? wih[r * 64 + k] : whh[r * 64 + (k - 64)];
            else if (r < 192)  { if (k < 64)  v = wih[r * 64 + k]; }
            else               { if (k >= 64) v = whh[(r - 64) * 64 + (k - 64)]; }
        }
        __nv_bfloat16 hi = __float2bfloat16(v);
        __nv_bfloat16 lo = __float2bfloat16(v - __bfloat162float(hi));
        uint32_t off = (uint32_t)r * GR + (uint32_t)k * 2;
        *(__nv_bfloat16*)(dst + off) = hi;
        *(__nv_bfloat16*)(dst + GW_LO + off) = lo;
    }
}

// ---------------- generic HMMA tile: [M x K] x [N x K]^T, warp tile 32m x 16*NPAIR
template<int KCH, int NPAIR>
__device__ __forceinline__ void layer_mma_s(
    uint32_t aA, uint32_t aW, uint32_t rstr, uint32_t aLo, uint32_t wLo,
    int lane, int mbase, int nbase, float* acc)
{
    const uint32_t aRow = aA + (uint32_t)(mbase + (lane & 15)) * rstr + ((lane >> 4) << 4);
    const uint32_t bRow = aW + (uint32_t)(nbase + (lane & 7) + ((lane >> 4) << 3)) * rstr
                        + (((lane >> 3) & 1) << 4);
    #pragma unroll
    for (int kc = 0; kc < KCH; kc++) {
        uint32_t ah[8], al[8];
        ldsm4(aRow + kc * 32, ah);
        ldsm4(aRow + 16 * rstr + kc * 32, ah + 4);
        ldsm4(aRow + aLo + kc * 32, al);
        ldsm4(aRow + aLo + 16 * rstr + kc * 32, al + 4);
        #pragma unroll
        for (int np = 0; np < NPAIR; np++) {
            uint32_t bh[4], bl[4];
            ldsm4(bRow + np * 16 * rstr + kc * 32, bh);
            ldsm4(bRow + wLo + np * 16 * rstr + kc * 32, bl);
            #pragma unroll
            for (int m = 0; m < 2; m++) {
                #pragma unroll
                for (int h = 0; h < 2; h++) {
                    float* d = acc + ((m * NPAIR + np) * 2 + h) * 4;
                    mma16816(d, ah + m * 4, bh + h * 2);
                    mma16816(d, ah + m * 4, bl + h * 2);
                    mma16816(d, al + m * 4, bh + h * 2);
                }
            }
        }
    }
}

// k8 tail for layer 1 (cols 128..135, byte offset 256), warp tile 32m x 32n
__device__ __forceinline__ void layer1_tail(
    uint32_t aA, uint32_t aW, int lane, int mbase, int nbase, float* acc)
{
    const uint32_t aAddr = aA + (uint32_t)(mbase + lane) * ER + 256;
    const uint32_t bAddr = aW + (uint32_t)(nbase + lane) * ER + 256;
    uint32_t ah[4], al[4], bh[4], bl[4];
    ldsm4(aAddr, ah);
    ldsm4(aAddr + EA_LO, al);
    ldsm4(bAddr, bh);
    ldsm4(bAddr + EW_LO128, bl);
    #pragma unroll
    for (int m = 0; m < 2; m++)
        #pragma unroll
        for (int n4 = 0; n4 < 4; n4++) {
            float* d = acc + ((m * 2 + (n4 >> 1)) * 2 + (n4 & 1)) * 4;
            mma16808(d, ah + 2 * m, bh[n4]);
            mma16808(d, ah + 2 * m, bl[n4]);
            mma16808(d, al + 2 * m, bh[n4]);
        }
}

// epilogue edge layers 1/2: +bias, relu, hi/lo split, write back into A tile
__device__ __forceinline__ void epi12(unsigned char* Ab, const float* bias,
                                      int lane, int mbase, int nbase, const float* acc)
{
    #pragma unroll
    for (int m = 0; m < 2; m++)
        #pragma unroll
        for (int np = 0; np < 2; np++)
            #pragma unroll
            for (int h = 0; h < 2; h++) {
                const float* d = acc + ((m * 2 + np) * 2 + h) * 4;
                int c = nbase + np * 16 + h * 8 + 2 * (lane & 3);
                int r = mbase + m * 16 + (lane >> 2);
                float b0 = bias[c], b1 = bias[c + 1];
                float v0 = fmaxf(d[0] + b0, 0.f), v1 = fmaxf(d[1] + b1, 0.f);
                float v2 = fmaxf(d[2] + b0, 0.f), v3 = fmaxf(d[3] + b1, 0.f);
                __nv_bfloat162 hA = __floats2bfloat162_rn(v0, v1);
                __nv_bfloat162 lA = __floats2bfloat162_rn(v0 - __low2float(hA),
                                                          v1 - __high2float(hA));
                __nv_bfloat162 hB = __floats2bfloat162_rn(v2, v3);
                __nv_bfloat162 lB = __floats2bfloat162_rn(v2 - __low2float(hB),
                                                          v3 - __high2float(hB));
                uint32_t o0 = (uint32_t)r * ER + (uint32_t)c * 2;
                uint32_t o1 = o0 + 8u * ER;
                *(uint32_t*)(Ab + o0)         = *(uint32_t*)&hA;
                *(uint32_t*)(Ab + EA_LO + o0) = *(uint32_t*)&lA;
                *(uint32_t*)(Ab + o1)         = *(uint32_t*)&hB;
                *(uint32_t*)(Ab + EA_LO + o1) = *(uint32_t*)&lB;
            }
}

// ---------------- fused edge MLP: 136->128->128->64, 64 edges/block, occ=2 --
#define SM_W    34816
#define SM_RS   104448
#define SM_CS   104704
#define SM_BIAS 104960
#define SM_MBW  106240
#define EDGE_SMEM_BYTES 106272
__global__ __launch_bounds__(256, 2) void edge_mma_kernel(
    const float* __restrict__ Ah, const float* __restrict__ Bh,
    const int* __restrict__ rowi, const int* __restrict__ coli,
    const float* __restrict__ feat,
    const unsigned char* __restrict__ wsrc,
    const float* __restrict__ b1, const float* __restrict__ b2,
    const float* __restrict__ b3,
    float* __restrict__ nm)
{
    extern __shared__ __align__(256) unsigned char sm[];
    const uint32_t smb = smem_u32(sm);
    const int tid = threadIdx.x;
    const int e0 = blockIdx.x * 64;

    int*   rs     = (int*)(sm + SM_RS);
    int*   cs     = (int*)(sm + SM_CS);
    float* bias_s = (float*)(sm + SM_BIAS);
    const uint32_t mbw = smb + SM_MBW;

    if (tid == 0) MBARRIER_INIT(mbw, 1u);
    __syncthreads();
    if (tid == 0) {
        MBARRIER_EXPECT_TX(mbw, 69632u);
        bulk_copy_g2s(smb + SM_W, wsrc, 69632u, mbw);
    }
    if (tid < 64)        rs[tid] = rowi[e0 + tid];
    else if (tid < 128)  cs[tid - 64] = coli[e0 + tid - 64];
    for (int i = tid; i < 320; i += 256)
        bias_s[i] = (i < 128) ? b1[i] : (i < 256 ? b2[i - 128] : b3[i - 256]);
    __syncthreads();

    // gather A1 = [Ah[row](64) | Bh[col](64) | feat[row](4) | feat[col](4)] = 136 cols
    for (int i = tid; i < 64 * 34; i += 256) {
        int e = i / 34, q = i - e * 34;
        float4 x;
        if (q < 16)       x = *(const float4*)(Ah + (size_t)rs[e] * 64 + q * 4);
        else if (q < 32)  x = *(const float4*)(Bh + (size_t)cs[e] * 64 + (q - 16) * 4);
        else if (q == 32) x = *(const float4*)(feat + (size_t)rs[e] * 4);
        else              x = *(const float4*)(feat + (size_t)cs[e] * 4);
        __nv_bfloat162 h01 = __floats2bfloat162_rn(x.x, x.y);
        __nv_bfloat162 h23 = __floats2bfloat162_rn(x.z, x.w);
        __nv_bfloat162 l01 = __floats2bfloat162_rn(x.x - __low2float(h01), x.y - __high2float(h01));
        __nv_bfloat162 l23 = __floats2bfloat162_rn(x.z - __low2float(h23), x.w - __high2float(h23));
        uint32_t off = (uint32_t)e * ER + (uint32_t)q * 8;
        *(uint2*)(sm + off)         = make_uint2(*(uint32_t*)&h01, *(uint32_t*)&h23);
        *(uint2*)(sm + EA_LO + off) = make_uint2(*(uint32_t*)&l01, *(uint32_t*)&l23);
    }
    __syncthreads();

    const int w = tid >> 5, lane = tid & 31;
    const int mbase = (w & 1) * 32;
    const int nb32  = (w >> 1) * 32;
    float acc[32];

    // ---- layer 1: K=136 (8 k16 chunks + k8 tail), N=128 ----
    MBARRIER_WAIT_PARITY(mbw, 0);
    #pragma unroll
    for (int i = 0; i < 32; i++) acc[i] = 0.f;
    layer_mma_s<8, 2>(smb, smb + SM_W, ER, EA_LO, EW_LO128, lane, mbase, nb32, acc);
    layer1_tail(smb, smb + SM_W, lane, mbase, nb32, acc);
    __syncthreads();
    if (tid == 0) {
        MBARRIER_EXPECT_TX(mbw, 69632u);
        bulk_copy_g2s(smb + SM_W, wsrc + 69632, 69632u, mbw);
    }
    epi12(sm, bias_s, lane, mbase, nb32, acc);
    __syncthreads();

    // ---- layer 2: K=128, N=128 ----
    MBARRIER_WAIT_PARITY(mbw, 1);
    #pragma unroll
    for (int i = 0; i < 32; i++) acc[i] = 0.f;
    layer_mma_s<8, 2>(smb, smb + SM_W, ER, EA_LO, EW_LO128, lane, mbase, nb32, acc);
    __syncthreads();
    if (tid == 0) {
        MBARRIER_EXPECT_TX(mbw, 34816u);
        bulk_copy_g2s(smb + SM_W, wsrc + 139264, 34816u, mbw);
    }
    epi12(sm, bias_s + 128, lane, mbase, nb32, acc);
    __syncthreads();

    // ---- layer 3: K=128, N=64, scatter-add ----
    MBARRIER_WAIT_PARITY(mbw, 0);
    #pragma unroll
    for (int i = 0; i < 16; i++) acc[i] = 0.f;
    const int nb16 = (w >> 1) * 16;
    layer_mma_s<8, 1>(smb, smb + SM_W, ER, EA_LO, EW_LO64, lane, mbase, nb16, acc);

    #pragma unroll
    for (int m = 0; m < 2; m++)
        #pragma unroll
        for (int h = 0; h < 2; h++) {
            const float* d = acc + (m * 2 + h) * 4;
            int c = nb16 + h * 8 + 2 * (lane & 3);
            int r = mbase + m * 16 + (lane >> 2);
            float b0 = bias_s[256 + c], b1v = bias_s[256 + c + 1];
            float* p0 = nm + (size_t)cs[r] * 64 + c;
            float* p1 = nm + (size_t)cs[r + 8] * 64 + c;
            atomicAdd(p0,     d[0] + b0);
            atomicAdd(p0 + 1, d[1] + b1v);
            atomicAdd(p1,     d[2] + b0);
            atomicAdd(p1 + 1, d[3] + b1v);
        }
}

// ---------------- HMMA GRU: [x|h](128x128) @ W'(256x128)^T ------------------
#define GSM_W    69632
#define GSM_BIAS 208896
#define GSM_MBW  209920
#define GRU_SMEM_BYTES 209952
__global__ __launch_bounds__(512, 1) void gru_mma_kernel(
    float* __restrict__ h, float* __restrict__ x,
    const unsigned char* __restrict__ wsrc,
    const float* __restrict__ bih, const float* __restrict__ bhh,
    int nrows)
{
    extern __shared__ __align__(256) unsigned char sm[];
    const uint32_t smb = smem_u32(sm);
    const int tid = threadIdx.x;
    const int r0 = blockIdx.x * 128;

    float* bias_s = (float*)(sm + GSM_BIAS);
    float* gs     = (float*)(sm + GSM_W);
    const uint32_t mbw = smb + GSM_MBW;

    if (tid == 0) MBARRIER_INIT(mbw, 1u);
    __syncthreads();
    if (tid == 0) {
        MBARRIER_EXPECT_TX(mbw, 139264u);
        bulk_copy_g2s(smb + GSM_W, wsrc, 139264u, mbw);
    }
    for (int i = tid; i < 256; i += 512) {
        float v;
        if (i < 128)      v = bih[i] + bhh[i];
        else if (i < 192) v = bih[i];
        else              v = bhh[i - 64];
        bias_s[i] = v;
    }

    for (int i = tid; i < 128 * 32; i += 512) {
        int e = i >> 5, q = i & 31;
        int rr = r0 + e;
        int rc = rr < nrows ? rr : nrows - 1;
        float4 xv;
        if (q < 16) {
            xv = *(const float4*)(x + (size_t)rc * 64 + q * 4);
            if (rr < nrows) *(float4*)(x + (size_t)rc * 64 + q * 4) = make_float4(0.f, 0.f, 0.f, 0.f);
        } else {
            xv = *(const float4*)(h + (size_t)rc * 64 + (q - 16) * 4);
        }
        __nv_bfloat162 h01 = __floats2bfloat162_rn(xv.x, xv.y);
        __nv_bfloat162 h23 = __floats2bfloat162_rn(xv.z, xv.w);
        __nv_bfloat162 l01 = __floats2bfloat162_rn(xv.x - __low2float(h01), xv.y - __high2float(h01));
        __nv_bfloat162 l23 = __floats2bfloat162_rn(xv.z - __low2float(h23), xv.w - __high2float(h23));
        uint32_t off = (uint32_t)e * GR + (uint32_t)q * 8;
        *(uint2*)(sm + off)         = make_uint2(*(uint32_t*)&h01, *(uint32_t*)&h23);
        *(uint2*)(sm + GA_LO + off) = make_uint2(*(uint32_t*)&l01, *(uint32_t*)&l23);
    }
    __syncthreads();

    const int w = tid >> 5, lane = tid & 31;
    const int mbase = (w & 3) * 32;
    const int nbase = (w >> 2) * 64;
    float acc[64];
    #pragma unroll
    for (int i = 0; i < 64; i++) acc[i] = 0.f;

    MBARRIER_WAIT_PARITY(mbw, 0);
    layer_mma_s<8, 4>(smb, smb + GSM_W, GR, GA_LO, GW_LO, lane, mbase, nbase, acc);
    __syncthreads();

    #pragma unroll
    for (int m = 0; m < 2; m++)
        #pragma unroll
        for (int np = 0; np < 4; np++)
            #pragma unroll
            for (int hh = 0; hh < 2; hh++) {
                const float* d = acc + ((m * 4 + np) * 2 + hh) * 4;
                int c = nbase + np * 16 + hh * 8 + 2 * (lane & 3);
                int r = mbase + m * 16 + (lane >> 2);
                gs[r * 256 + c]           = d[0];
                gs[r * 256 + c + 1]       = d[1];
                gs[(r + 8) * 256 + c]     = d[2];
                gs[(r + 8) * 256 + c + 1] = d[3];
            }
    __syncthreads();

    for (int i = tid; i < 128 * 64; i += 512) {
        int e = i >> 6, d = i & 63;
        int r = r0 + e;
        if (r >= nrows) continue;
        const float* g = gs + e * 256;
        float pr = g[d]       + bias_s[d];
        float pz = g[64 + d]  + bias_s[64 + d];
        float in = g[128 + d] + bias_s[128 + d];
        float hn = g[192 + d] + bias_s[192 + d];
        float rr = 1.f / (1.f + expf(-pr));
        float zz = 1.f / (1.f + expf(-pz));
        float nn = tanhf(in + rr * hn);
        float hv = h[(size_t)r * 64 + d];
        h[(size_t)r * 64 + d] = (1.f - zz) * nn + zz * hv;
    }
}

// ---------------- readout ----------------
__global__ __launch_bounds__(256) void readout_kernel(
    const float* __restrict__ h,
    const float* __restrict__ W1, const float* __restrict__ b1,
    const float* __restrict__ W2, const float* __restrict__ b2,
    const float* __restrict__ W3, const float* __restrict__ b3,
    float* __restrict__ out, int nrows)
{
    __shared__ float hs[32 * 68];
    __shared__ float l1s[32 * 132];
    __shared__ float l2s[32 * 132];
    __shared__ float lg[64];

    const int tid = threadIdx.x;
    const int r0  = blockIdx.x * 32;

    for (int i = tid; i < 32 * 64; i += 256) {
        int e = i >> 6, k = i & 63;
        int r = r0 + e;
        hs[e * 68 + k] = (r < nrows) ? h[(size_t)r * 64 + k] : 0.f;
    }
    __syncthreads();

    const int warp = tid >> 5, lane = tid & 31;
    #pragma unroll
    for (int jc = 0; jc < 4; jc++) {
        const int j0 = warp * 16 + jc * 4;
        float a[4] = {0.f, 0.f, 0.f, 0.f};
        #pragma unroll
        for (int k = 0; k < 64; k += 4) {
            float4 xv = *(const float4*)(hs + lane * 68 + k);
            #pragma unroll
            for (int jj = 0; jj < 4; jj++) {
                float4 wv = *(const float4*)(W1 + (size_t)(j0 + jj) * 64 + k);
                a[jj] += wv.x * xv.x + wv.y * xv.y + wv.z * xv.z + wv.w * xv.w;
            }
        }
        #pragma unroll
        for (int jj = 0; jj < 4; jj++)
            l1s[lane * 132 + j0 + jj] = fmaxf(a[jj] + b1[j0 + jj], 0.f);
    }
    __syncthreads();
    #pragma unroll
    for (int jc = 0; jc < 4; jc++) {
        const int j0 = warp * 16 + jc * 4;
        float a[4] = {0.f, 0.f, 0.f, 0.f};
        #pragma unroll 2
        for (int k = 0; k < 128; k += 4) {
            float4 xv = *(const float4*)(l1s + lane * 132 + k);
            #pragma unroll
            for (int jj = 0; jj < 4; jj++) {
                float4 wv = *(const float4*)(W2 + (size_t)(j0 + jj) * 128 + k);
                a[jj] += wv.x * xv.x + wv.y * xv.y + wv.z * xv.z + wv.w * xv.w;
            }
        }
        #pragma unroll
        for (int jj = 0; jj < 4; jj++)
            l2s[lane * 132 + j0 + jj] = fmaxf(a[jj] + b2[j0 + jj], 0.f);
    }
    __syncthreads();
    if (tid < 64) {
        int e = tid >> 1, j = tid & 1;
        float a = 0.f;
        #pragma unroll 4
        for (int k = 0; k < 128; k += 4) {
            float4 xv = *(const float4*)(l2s + e * 132 + k);
            float4 wv = *(const float4*)(W3 + (size_t)j * 128 + k);
            a += wv.x * xv.x + wv.y * xv.y + wv.z * xv.z + wv.w * xv.w;
        }
        lg[e * 2 + j] = a + b3[j];
    }
    __syncthreads();
    if (tid < 64) {
        int e = tid >> 1, j = tid & 1;
        int r = r0 + e;
        if (r < nrows) {
            float self  = lg[e * 2 + j];
            float other = lg[e * 2 + (j ^ 1)];
            out[(size_t)r * 2 + j] = 1.f / (1.f + expf(other - self));
        }
    }
}

extern "C" void kernel_launch(void* const* d_in, const int* in_sizes, int n_in,
                              void* d_out, int out_size)
{
    const int*   f2v_row  = (const int*)d_in[0];
    const int*   f2v_col  = (const int*)d_in[1];
    const int*   v2f_row  = (const int*)d_in[2];
    const int*   v2f_col  = (const int*)d_in[3];
    const float* f2v_feat = (const float*)d_in[4];
    const float* v2f_feat = (const float*)d_in[5];
    const float* f2v_w1 = (const float*)d_in[6];   const float* f2v_b1 = (const float*)d_in[7];
    const float* f2v_w2 = (const float*)d_in[8];   const float* f2v_b2 = (const float*)d_in[9];
    const float* f2v_w3 = (const float*)d_in[10];  const float* f2v_b3 = (const float*)d_in[11];
    const float* v2f_w1 = (const float*)d_in[12];  const float* v2f_b1 = (const float*)d_in[13];
    const float* v2f_w2 = (const float*)d_in[14];  const float* v2f_b2 = (const float*)d_in[15];
    const float* v2f_w3 = (const float*)d_in[16];  const float* v2f_b3 = (const float*)d_in[17];
    const float* gf_wih = (const float*)d_in[18];  const float* gf_whh = (const float*)d_in[19];
    const float* gf_bih = (const float*)d_in[20];  const float* gf_bhh = (const float*)d_in[21];
    const float* gv_wih = (const float*)d_in[22];  const float* gv_whh = (const float*)d_in[23];
    const float* gv_bih = (const float*)d_in[24];  const float* gv_bhh = (const float*)d_in[25];
    const float* ro_w1  = (const float*)d_in[26];  const float* ro_b1  = (const float*)d_in[27];
    const float* ro_w2  = (const float*)d_in[28];  const float* ro_b2  = (const float*)d_in[29];
    const float* ro_w3  = (const float*)d_in[30];  const float* ro_b3  = (const float*)d_in[31];
    float* out = (float*)d_out;

    float *var_h, *fac_h, *nm_var, *nm_fac;
    unsigned char *wp_f2v, *wp_v2f, *wg_gf, *wg_gv;
    cudaGetSymbolAddress((void**)&var_h,  g_var_h);
    cudaGetSymbolAddress((void**)&fac_h,  g_fac_h);
    cudaGetSymbolAddress((void**)&nm_var, g_nm_var);
    cudaGetSymbolAddress((void**)&nm_fac, g_nm_fac);
    cudaGetSymbolAddress((void**)&wp_f2v, g_wpack_f2v);
    cudaGetSymbolAddress((void**)&wp_v2f, g_wpack_v2f);
    cudaGetSymbolAddress((void**)&wg_gf,  g_wgru_gf);
    cudaGetSymbolAddress((void**)&wg_gv,  g_wgru_gv);

    cudaFuncSetAttribute(edge_mma_kernel, cudaFuncAttributeMaxDynamicSharedMemorySize, EDGE_SMEM_BYTES);
    cudaFuncSetAttribute(gru_mma_kernel,  cudaFuncAttributeMaxDynamicSharedMemorySize, GRU_SMEM_BYTES);

    pack_weights_kernel<<<32, 256>>>(wp_f2v,           f2v_w1, 128, 136);
    pack_weights_kernel<<<32, 256>>>(wp_f2v + 69632,   f2v_w2, 128, 128);
    pack_weights_kernel<<<32, 256>>>(wp_f2v + 139264,  f2v_w3,  64, 128);
    pack_weights_kernel<<<32, 256>>>(wp_v2f,           v2f_w1, 128, 136);
    pack_weights_kernel<<<32, 256>>>(wp_v2f + 69632,   v2f_w2, 128, 128);
    pack_weights_kernel<<<32, 256>>>(wp_v2f + 139264,  v2f_w3,  64, 128);
    pack_gru_kernel<<<32, 256>>>(wg_gf, gf_wih, gf_whh);
    pack_gru_kernel<<<32, 256>>>(wg_gv, gv_wih, gv_whh);

    zero_kernel<<<256, 256>>>(var_h, NV * 64);
    zero_kernel<<<512, 256>>>(fac_h, NF * 64);
    zero_kernel<<<256, 256>>>(nm_var, NV * 64);
    zero_kernel<<<512, 256>>>(nm_fac, NF * 64);

    for (int s = 0; s < 5; s++) {
        edge_mma_kernel<<<NE / 64, 256, EDGE_SMEM_BYTES>>>(
            fac_h, var_h, f2v_row, f2v_col, f2v_feat, wp_f2v,
            f2v_b1, f2v_b2, f2v_b3, nm_var);
        gru_mma_kernel<<<(NV + 127) / 128, 512, GRU_SMEM_BYTES>>>(
            var_h, nm_var, wg_gf, gf_bih, gf_bhh, NV);

        edge_mma_kernel<<<NE / 64, 256, EDGE_SMEM_BYTES>>>(
            var_h, fac_h, v2f_row, v2f_col, v2f_feat, wp_v2f,
            v2f_b1, v2f_b2, v2f_b3, nm_fac);
        gru_mma_kernel<<<NF / 128, 512, GRU_SMEM_BYTES>>>(
            fac_h, nm_fac, wg_gv, gv_bih, gv_bhh, NF);
    }

    readout_kernel<<<(NV + 31) / 32, 256>>>(
        var_h, ro_w1, ro_b1, ro_w2, ro_b2, ro_w3, ro_b3, out, NV);
}